// round 4
// baseline (speedup 1.0000x reference)
#include <cuda_runtime.h>
#include <cuda_fp16.h>
#include <cstdint>
#include <math.h>

#define Bb 16
#define Nn 1024
#define Tt 512
#define Cc 768
#define ROWS1 (Bb*Tt)   // 8192
#define ROWS2 (Bb*Nn)   // 16384

typedef unsigned short ushrt;

// ---------------- device scratch ----------------
__device__ float g_y1[(size_t)ROWS1*Cc];        // text@Wc^T (pre-BN)
__device__ float g_attn[(size_t)Bb*Tt*Nn];      // attn_t[B,T,N] fp32
__device__ float g_p1[64*2*Cc];
__device__ float g_p2[128*2*Cc];
__device__ float g_mu1[Cc], g_rs1[Cc], g_mu2[Cc], g_rs2[Cc];

// packed fp16 hi/lo operands, row-major
__device__ ushrt p_text_hi[(size_t)ROWS1*Cc], p_text_lo[(size_t)ROWS1*Cc];
__device__ ushrt p_img_hi [(size_t)ROWS2*Cc], p_img_lo [(size_t)ROWS2*Cc];
__device__ ushrt p_Wc_hi[Cc*Cc], p_Wc_lo[Cc*Cc];
__device__ ushrt p_Wo_hi[Cc*Cc], p_Wo_lo[Cc*Cc];
__device__ ushrt p_e1_hi[(size_t)ROWS1*Cc], p_e1_lo[(size_t)ROWS1*Cc];
__device__ ushrt p_vt_hi[(size_t)Bb*Cc*Tt], p_vt_lo[(size_t)Bb*Cc*Tt];   // vT[b][c][t]
__device__ ushrt p_wt_hi[(size_t)Bb*Tt*Nn], p_wt_lo[(size_t)Bb*Tt*Nn];   // w[b][t][n]

// ---------------- helpers ----------------
__device__ __forceinline__ uint32_t smem_u32(const void* p) {
    uint32_t a;
    asm("{ .reg .u64 t; cvta.to.shared.u64 t, %1; cvt.u32.u64 %0, t; }" : "=r"(a) : "l"(p));
    return a;
}
__device__ __forceinline__ void cpa16(uint32_t d, const void* s) {
    asm volatile("cp.async.cg.shared.global [%0], [%1], 16;" :: "r"(d), "l"(s));
}
__device__ __forceinline__ void cpa_commit() { asm volatile("cp.async.commit_group;" ::: "memory"); }
template<int N> __device__ __forceinline__ void cpa_wait() {
    asm volatile("cp.async.wait_group %0;" :: "n"(N) : "memory");
}
#define LDM4(r, addr) \
    asm volatile("ldmatrix.sync.aligned.m8n8.x4.shared.b16 {%0,%1,%2,%3}, [%4];" \
        : "=r"((r)[0]), "=r"((r)[1]), "=r"((r)[2]), "=r"((r)[3]) : "r"(addr))
#define LDM4T(r, addr) \
    asm volatile("ldmatrix.sync.aligned.m8n8.x4.trans.shared.b16 {%0,%1,%2,%3}, [%4];" \
        : "=r"((r)[0]), "=r"((r)[1]), "=r"((r)[2]), "=r"((r)[3]) : "r"(addr))
#define MMA16816(d, a, b0, b1) \
    asm volatile("mma.sync.aligned.m16n8k16.row.col.f32.f16.f16.f32 " \
        "{%0,%1,%2,%3}, {%4,%5,%6,%7}, {%8,%9}, {%0,%1,%2,%3};" \
        : "+f"((d)[0]), "+f"((d)[1]), "+f"((d)[2]), "+f"((d)[3]) \
        : "r"((a)[0]), "r"((a)[1]), "r"((a)[2]), "r"((a)[3]), "r"(b0), "r"(b1))

__device__ __forceinline__ void split2(float x, ushrt& h, ushrt& l) {
    __half hh = __float2half_rn(x);
    float fh = __half2float(hh);
    __half ll = __float2half_rn(x - fh);
    h = *reinterpret_cast<ushrt*>(&hh);
    l = *reinterpret_cast<ushrt*>(&ll);
}

// ---------------- fp16x3 MMA GEMM ----------------
// C[M,N] = alpha*(A @ B^T) (+ rowBias[m]). A: hi/lo fp16.
//  TA=false: A row-major [M][ldA], ldA=K.  TA=true: A stored [K][ldA] (K-major), tile read transposed.
// B: row-major [N][K]. BM=BN=128, BK=32, 256 threads, 8 warps (2x4), warp tile 64x32.
// 3-stage cp.async pipeline. If Ch!=null, write fp16 hi/lo split instead of fp32.
template<bool TA>
__global__ void __launch_bounds__(256, 1) gemm3(
    const ushrt* __restrict__ Ah, const ushrt* __restrict__ Al,
    const ushrt* __restrict__ Bh, const ushrt* __restrict__ Bl,
    float* __restrict__ C, ushrt* __restrict__ Ch, ushrt* __restrict__ Cl,
    int K, int Nc, int ldA, long sA, long sB, long sC,
    const float* __restrict__ bias, float alpha)
{
    constexpr int A_TILE = TA ? 8704 : 10240;    // TA: [32][136] fp16 ; NT: [128][40]
    constexpr int B_TILE = 10240;
    constexpr int STAGE  = 2*A_TILE + 2*B_TILE;
    extern __shared__ __align__(16) char smem[];
    const int tid = threadIdx.x, wid = tid >> 5, lid = tid & 31;
    const int m0 = blockIdx.y * 128, n0 = blockIdx.x * 128, bz = blockIdx.z;
    const int nk = K >> 5;
    const uint32_t sb = smem_u32(smem);

    const ushrt* gAh;
    const ushrt* gAl;
    if constexpr (TA) {
        gAh = Ah + (size_t)bz * sA + m0;
        gAl = Al + (size_t)bz * sA + m0;
    } else {
        gAh = Ah + (size_t)bz * sA + (size_t)m0 * ldA;
        gAl = Al + (size_t)bz * sA + (size_t)m0 * ldA;
    }
    const ushrt* gBh = Bh + (size_t)bz * sB + (size_t)n0 * K;
    const ushrt* gBl = Bl + (size_t)bz * sB + (size_t)n0 * K;

    // per-thread 16B-chunk mapping (512 chunks per tile; 2 per thread)
    uint32_t a_sm[2]; size_t a_g[2];
    uint32_t b_sm[2]; size_t b_g[2];
#pragma unroll
    for (int j = 0; j < 2; j++) {
        int i = tid + 256 * j;
        if constexpr (TA) {
            int r = i >> 4, c8 = (i & 15) * 8;          // 32 rows x 128 cols
            a_sm[j] = (uint32_t)(r * 272 + c8 * 2);
            a_g[j]  = (size_t)r * ldA + c8;
        } else {
            int r = i >> 2, c8 = (i & 3) * 8;           // 128 rows x 32 cols
            a_sm[j] = (uint32_t)(r * 80 + c8 * 2);
            a_g[j]  = (size_t)r * ldA + c8;
        }
        int r = i >> 2, c8 = (i & 3) * 8;
        b_sm[j] = (uint32_t)(r * 80 + c8 * 2);
        b_g[j]  = (size_t)r * K + c8;
    }

    auto load_chunk = [&](int c, int s) {
        uint32_t ds = sb + (uint32_t)s * STAGE;
        size_t aoff = TA ? (size_t)c * 32 * ldA : (size_t)c * 32;
        size_t boff = (size_t)c * 32;
#pragma unroll
        for (int j = 0; j < 2; j++) {
            cpa16(ds + a_sm[j],              gAh + aoff + a_g[j]);
            cpa16(ds + A_TILE + a_sm[j],     gAl + aoff + a_g[j]);
            cpa16(ds + 2*A_TILE + b_sm[j],          gBh + boff + b_g[j]);
            cpa16(ds + 2*A_TILE + B_TILE + b_sm[j], gBl + boff + b_g[j]);
        }
    };

    // fragment base offsets (bytes)
    const int wm0 = (wid >> 2) * 64, wn0 = (wid & 3) * 32;
    uint32_t a_fb;
    if constexpr (TA) {
        int k_off = (lid & 7) + ((lid >> 4) << 3);
        int m_off = ((lid >> 3) & 1) << 3;
        a_fb = (uint32_t)(k_off * 272 + (wm0 + m_off) * 2);
    } else {
        a_fb = (uint32_t)(((wm0 + (lid & 15)) * 40 + (lid >> 4) * 8) * 2);
    }
    const uint32_t b_fb = (uint32_t)(2*A_TILE + ((wn0 + (lid & 15)) * 40 + (lid >> 4) * 8) * 2);

    float acc[4][4][4] = {};

    load_chunk(0, 0);
    cpa_commit();
    if (nk > 1) load_chunk(1, 1);
    cpa_commit();

    for (int c = 0; c < nk; c++) {
        cpa_wait<1>();
        __syncthreads();
        if (c + 2 < nk) load_chunk(c + 2, (c + 2) % 3);
        cpa_commit();

        const uint32_t st = sb + (uint32_t)(c % 3) * STAGE;
#pragma unroll
        for (int kk = 0; kk < 2; kk++) {
            uint32_t Ahf[4][4], Alf[4][4], Bhf[2][4], Blf[2][4];
            if constexpr (TA) {
                const uint32_t ak = st + a_fb + kk * 4352;     // kk*16 rows * 272
#pragma unroll
                for (int mi = 0; mi < 4; mi++) {
                    LDM4T(Ahf[mi], ak + mi * 32);
                    LDM4T(Alf[mi], ak + A_TILE + mi * 32);
                }
            } else {
                const uint32_t ak = st + a_fb + kk * 32;
#pragma unroll
                for (int mi = 0; mi < 4; mi++) {
                    LDM4(Ahf[mi], ak + mi * 1280);
                    LDM4(Alf[mi], ak + A_TILE + mi * 1280);
                }
            }
            const uint32_t bk = st + b_fb + kk * 32;
#pragma unroll
            for (int p = 0; p < 2; p++) {
                LDM4(Bhf[p], bk + p * 1280);
                LDM4(Blf[p], bk + B_TILE + p * 1280);
            }
#pragma unroll
            for (int mi = 0; mi < 4; mi++) {
#pragma unroll
                for (int nj = 0; nj < 4; nj++) {
                    const int p = nj >> 1, h = nj & 1;
                    MMA16816(acc[mi][nj], Ahf[mi], Bhf[p][h], Bhf[p][h + 2]);
                    MMA16816(acc[mi][nj], Ahf[mi], Blf[p][h], Blf[p][h + 2]);
                    MMA16816(acc[mi][nj], Alf[mi], Bhf[p][h], Bhf[p][h + 2]);
                }
            }
        }
        __syncthreads();
    }

    // epilogue
    const int qr = lid >> 2, qc = (lid & 3) * 2;
#pragma unroll
    for (int mi = 0; mi < 4; mi++) {
        const int row0 = m0 + wm0 + mi * 16 + qr;
        const int row1 = row0 + 8;
        const float bv0 = bias ? bias[row0] : 0.f;
        const float bv1 = bias ? bias[row1] : 0.f;
#pragma unroll
        for (int nj = 0; nj < 4; nj++) {
            const int col = n0 + wn0 + nj * 8 + qc;
            float v00 = acc[mi][nj][0] * alpha + bv0;
            float v01 = acc[mi][nj][1] * alpha + bv0;
            float v10 = acc[mi][nj][2] * alpha + bv1;
            float v11 = acc[mi][nj][3] * alpha + bv1;
            if (Ch) {
                ushort2 h0, l0, h1, l1;
                split2(v00, h0.x, l0.x); split2(v01, h0.y, l0.y);
                split2(v10, h1.x, l1.x); split2(v11, h1.y, l1.y);
                size_t o0 = (size_t)bz * sC + (size_t)row0 * Nc + col;
                size_t o1 = (size_t)bz * sC + (size_t)row1 * Nc + col;
                *reinterpret_cast<ushort2*>(Ch + o0) = h0;
                *reinterpret_cast<ushort2*>(Cl + o0) = l0;
                *reinterpret_cast<ushort2*>(Ch + o1) = h1;
                *reinterpret_cast<ushort2*>(Cl + o1) = l1;
            } else {
                float* Cb = C + (size_t)bz * sC;
                float2 a0, a1;
                a0.x = v00; a0.y = v01; a1.x = v10; a1.y = v11;
                *reinterpret_cast<float2*>(Cb + (size_t)row0 * Nc + col) = a0;
                *reinterpret_cast<float2*>(Cb + (size_t)row1 * Nc + col) = a1;
            }
        }
    }
}

#define NT_SMEM (3*(2*10240 + 2*10240))   // 122880
#define TA_SMEM (3*(2*8704  + 2*10240))   // 113664

// ---------------- pack kernels ----------------
__global__ __launch_bounds__(256) void pack_split(const float4* __restrict__ X,
                                                  ushort4* __restrict__ H, ushort4* __restrict__ L, long n4)
{
    long i = (long)blockIdx.x * 256 + threadIdx.x;
    if (i >= n4) return;
    float4 v = X[i];
    ushort4 h, l;
    split2(v.x, h.x, l.x); split2(v.y, h.y, l.y);
    split2(v.z, h.z, l.z); split2(v.w, h.w, l.w);
    H[i] = h; L[i] = l;
}

__global__ __launch_bounds__(256) void pack_bn_relu(const float4* __restrict__ X,
                                                    ushort4* __restrict__ H, ushort4* __restrict__ L,
                                                    const float* __restrict__ g, const float* __restrict__ bb)
{
    long i = (long)blockIdx.x * 256 + threadIdx.x;   // over ROWS1*Cc/4
    float4 v = X[i];
    int ch = (int)((i * 4) % Cc);
    v.x = fmaxf(g[ch+0]*(v.x - g_mu1[ch+0])*g_rs1[ch+0] + bb[ch+0], 0.f);
    v.y = fmaxf(g[ch+1]*(v.y - g_mu1[ch+1])*g_rs1[ch+1] + bb[ch+1], 0.f);
    v.z = fmaxf(g[ch+2]*(v.z - g_mu1[ch+2])*g_rs1[ch+2] + bb[ch+2], 0.f);
    v.w = fmaxf(g[ch+3]*(v.w - g_mu1[ch+3])*g_rs1[ch+3] + bb[ch+3], 0.f);
    ushort4 h, l;
    split2(v.x, h.x, l.x); split2(v.y, h.y, l.y);
    split2(v.z, h.z, l.z); split2(v.w, h.w, l.w);
    H[i] = h; L[i] = l;
}

// ---------------- per-(b,t) column: softmax + K-th-largest radix select -> fp16 hi/lo ----------------
__global__ __launch_bounds__(256) void topk_softmax(const float* __restrict__ kvals,
                                                    ushrt* __restrict__ Wh, ushrt* __restrict__ Wl)
{
    const int b = blockIdx.x >> 9;
    const int t = blockIdx.x & 511;
    const size_t base = ((size_t)b * Tt + t) * Nn;
    const float* col = g_attn + base;
    const int tid = threadIdx.x;
    __shared__ float sh[8];
    __shared__ unsigned hist[256];
    __shared__ unsigned s_sel, s_rem;

    float x[4]; unsigned u[4];
    float mx = -3.4e38f;
#pragma unroll
    for (int i = 0; i < 4; i++) {
        x[i] = col[tid + 256 * i];
        mx = fmaxf(mx, x[i]);
        unsigned bits = __float_as_uint(x[i]);
        u[i] = (bits & 0x80000000u) ? ~bits : (bits | 0x80000000u);
    }
    for (int o = 16; o > 0; o >>= 1) mx = fmaxf(mx, __shfl_xor_sync(0xffffffffu, mx, o));
    if ((tid & 31) == 0) sh[tid >> 5] = mx;
    __syncthreads();
    if (tid == 0) { float m = sh[0]; for (int i = 1; i < 8; i++) m = fmaxf(m, sh[i]); sh[0] = m; }
    __syncthreads();
    mx = sh[0];
    __syncthreads();
    float s = 0.f;
#pragma unroll
    for (int i = 0; i < 4; i++) s += expf(x[i] - mx);
    for (int o = 16; o > 0; o >>= 1) s += __shfl_xor_sync(0xffffffffu, s, o);
    if ((tid & 31) == 0) sh[tid >> 5] = s;
    __syncthreads();
    if (tid == 0) { float m = 0.f; for (int i = 0; i < 8; i++) m += sh[i]; sh[0] = m; }
    __syncthreads();
    const float inv = 1.f / sh[0];

    int K = (int)rintf((float)Nn * kvals[b]);
    if (K < 0) K = 0;
    if (K > Nn) K = Nn;
    if (K == 0) {
#pragma unroll
        for (int i = 0; i < 4; i++) { Wh[base + tid + 256*i] = 0; Wl[base + tid + 256*i] = 0; }
        return;
    }
    unsigned thr = 0u;
    if (K < Nn) {
        unsigned pref = 0u, rem = (unsigned)K;
        for (int shift = 24; shift >= 0; shift -= 8) {
            hist[tid] = 0u;
            __syncthreads();
            unsigned hm = (shift == 24) ? 0u : (0xFFFFFFFFu << (shift + 8));
#pragma unroll
            for (int i = 0; i < 4; i++)
                if ((u[i] & hm) == pref) atomicAdd(&hist[(u[i] >> shift) & 255u], 1u);
            __syncthreads();
            for (int off = 1; off < 256; off <<= 1) {
                unsigned vv = (tid + off < 256) ? hist[tid + off] : 0u;
                __syncthreads();
                hist[tid] += vv;
                __syncthreads();
            }
            unsigned nxt = (tid < 255) ? hist[tid + 1] : 0u;
            if (hist[tid] >= rem && nxt < rem) { s_sel = (unsigned)tid; s_rem = rem - nxt; }
            __syncthreads();
            pref |= (s_sel << shift);
            rem = s_rem;
            __syncthreads();
        }
        thr = pref;
    }
#pragma unroll
    for (int i = 0; i < 4; i++) {
        float w = (u[i] >= thr) ? expf(x[i] - mx) * inv : 0.f;
        ushrt h, l;
        split2(w, h, l);
        Wh[base + tid + 256*i] = h;
        Wl[base + tid + 256*i] = l;
    }
}

// ---------------- BN stats ----------------
__global__ __launch_bounds__(256) void bn_partial(const float* __restrict__ X, float* __restrict__ part)
{
    const int tid = threadIdx.x;
    const float* base = X + (size_t)blockIdx.x * 128 * Cc;
    float s0=0,s1=0,s2=0,q0=0,q1=0,q2=0;
    for (int r = 0; r < 128; r++) {
        const float* row = base + (size_t)r * Cc;
        float a = row[tid], b = row[tid+256], c = row[tid+512];
        s0 += a; q0 = fmaf(a,a,q0);
        s1 += b; q1 = fmaf(b,b,q1);
        s2 += c; q2 = fmaf(c,c,q2);
    }
    float* p = part + (size_t)blockIdx.x * (2*Cc);
    p[tid]    = s0; p[tid+256]    = s1; p[tid+512]    = s2;
    p[Cc+tid] = q0; p[Cc+tid+256] = q1; p[Cc+tid+512] = q2;
}

__global__ void bn_finalize(const float* __restrict__ part, int nblk, float invN,
                            float* __restrict__ mu, float* __restrict__ rs)
{
    int c = blockIdx.x * 256 + threadIdx.x;
    if (c >= Cc) return;
    float s = 0.f, q = 0.f;
    for (int i = 0; i < nblk; i++) {
        s += part[(size_t)i * 2 * Cc + c];
        q += part[(size_t)i * 2 * Cc + Cc + c];
    }
    float m = s * invN;
    mu[c] = m;
    rs[c] = rsqrtf(q * invN - m * m + 1e-5f);
}

__global__ __launch_bounds__(256) void final_apply(float* __restrict__ out, const float* __restrict__ img,
                                                   const float* __restrict__ g, const float* __restrict__ bb)
{
    int i4 = blockIdx.x * 256 + threadIdx.x;
    float4 o = reinterpret_cast<float4*>(out)[i4];
    float4 im = reinterpret_cast<const float4*>(img)[i4];
    int c = (i4 * 4) % Cc;
    o.x = fmaxf(g[c+0]*(o.x - g_mu2[c+0])*g_rs2[c+0] + bb[c+0], 0.f) + im.x;
    o.y = fmaxf(g[c+1]*(o.y - g_mu2[c+1])*g_rs2[c+1] + bb[c+1], 0.f) + im.y;
    o.z = fmaxf(g[c+2]*(o.z - g_mu2[c+2])*g_rs2[c+2] + bb[c+2], 0.f) + im.z;
    o.w = fmaxf(g[c+3]*(o.w - g_mu2[c+3])*g_rs2[c+3] + bb[c+3], 0.f) + im.w;
    reinterpret_cast<float4*>(out)[i4] = o;
}

// ---------------- orchestration ----------------
extern "C" void kernel_launch(void* const* d_in, const int* in_sizes, int n_in,
                              void* d_out, int out_size)
{
    (void)in_sizes; (void)n_in; (void)out_size;
    const float* image = (const float*)d_in[0];
    const float* text  = (const float*)d_in[1];
    const float* kv    = (const float*)d_in[2];
    const float* Wc    = (const float*)d_in[3];
    const float* g1    = (const float*)d_in[5];
    const float* b1    = (const float*)d_in[6];
    const float* Wout  = (const float*)d_in[7];
    const float* bout  = (const float*)d_in[8];
    const float* g2    = (const float*)d_in[9];
    const float* b2    = (const float*)d_in[10];
    float* out = (float*)d_out;

    float *y1, *attn, *p1, *p2, *mu1, *rs1, *mu2, *rs2;
    ushrt *tx_h, *tx_l, *im_h, *im_l, *wc_h, *wc_l, *wo_h, *wo_l,
          *e1_h, *e1_l, *vt_h, *vt_l, *wt_h, *wt_l;
    cudaGetSymbolAddress((void**)&y1,   g_y1);
    cudaGetSymbolAddress((void**)&attn, g_attn);
    cudaGetSymbolAddress((void**)&p1,   g_p1);
    cudaGetSymbolAddress((void**)&p2,   g_p2);
    cudaGetSymbolAddress((void**)&mu1,  g_mu1);
    cudaGetSymbolAddress((void**)&rs1,  g_rs1);
    cudaGetSymbolAddress((void**)&mu2,  g_mu2);
    cudaGetSymbolAddress((void**)&rs2,  g_rs2);
    cudaGetSymbolAddress((void**)&tx_h, p_text_hi); cudaGetSymbolAddress((void**)&tx_l, p_text_lo);
    cudaGetSymbolAddress((void**)&im_h, p_img_hi);  cudaGetSymbolAddress((void**)&im_l, p_img_lo);
    cudaGetSymbolAddress((void**)&wc_h, p_Wc_hi);   cudaGetSymbolAddress((void**)&wc_l, p_Wc_lo);
    cudaGetSymbolAddress((void**)&wo_h, p_Wo_hi);   cudaGetSymbolAddress((void**)&wo_l, p_Wo_lo);
    cudaGetSymbolAddress((void**)&e1_h, p_e1_hi);   cudaGetSymbolAddress((void**)&e1_l, p_e1_lo);
    cudaGetSymbolAddress((void**)&vt_h, p_vt_hi);   cudaGetSymbolAddress((void**)&vt_l, p_vt_lo);
    cudaGetSymbolAddress((void**)&wt_h, p_wt_hi);   cudaGetSymbolAddress((void**)&wt_l, p_wt_lo);

    cudaFuncSetAttribute(gemm3<false>, cudaFuncAttributeMaxDynamicSharedMemorySize, NT_SMEM);
    cudaFuncSetAttribute(gemm3<true>,  cudaFuncAttributeMaxDynamicSharedMemorySize, TA_SMEM);

    const float inv_sqrtC = 0.03608439182435161f;  // 1/sqrt(768)

    // pack fp32 -> fp16 hi/lo
    pack_split<<<6144, 256>>>((const float4*)text,  (ushort4*)tx_h, (ushort4*)tx_l, (long)ROWS1*Cc/4);
    pack_split<<<12288, 256>>>((const float4*)image, (ushort4*)im_h, (ushort4*)im_l, (long)ROWS2*Cc/4);
    pack_split<<<576, 256>>>((const float4*)Wc,   (ushort4*)wc_h, (ushort4*)wc_l, (long)Cc*Cc/4);
    pack_split<<<576, 256>>>((const float4*)Wout, (ushort4*)wo_h, (ushort4*)wo_l, (long)Cc*Cc/4);

    // G1: y1[8192,768] = text @ Wc^T  (bias bc cancels inside BN1)
    gemm3<false><<<dim3(6, 64, 1), 256, NT_SMEM>>>(
        tx_h, tx_l, wc_h, wc_l, y1, nullptr, nullptr,
        Cc, Cc, Cc, 0, 0, 0, nullptr, 1.f);

    // G2: vT[b][768,512] = Wout @ text[b]^T + bout[row]  -> fp16 hi/lo directly
    gemm3<false><<<dim3(4, 6, Bb), 256, NT_SMEM>>>(
        wo_h, wo_l, tx_h, tx_l, nullptr, vt_h, vt_l,
        Cc, Tt, Cc, 0, (long)Tt*Cc, (long)Cc*Tt, bout, 1.f);

    // BN1 stats + fused BN+relu+split-pack of e1
    bn_partial<<<64, 256>>>(y1, p1);
    bn_finalize<<<3, 256>>>(p1, 64, 1.f/(float)ROWS1, mu1, rs1);
    pack_bn_relu<<<6144, 256>>>((const float4*)y1, (ushort4*)e1_h, (ushort4*)e1_l, g1, b1);

    // G3: attn_t[b][512,1024] = (e1[b] @ image[b]^T) / sqrt(C)
    gemm3<false><<<dim3(8, 4, Bb), 256, NT_SMEM>>>(
        e1_h, e1_l, im_h, im_l, attn, nullptr, nullptr,
        Cc, Nn, Cc, (long)Tt*Cc, (long)Nn*Cc, (long)Tt*Nn, nullptr, inv_sqrtC);

    // masked softmax weights -> fp16 hi/lo in [b][t][n] layout
    topk_softmax<<<Bb*Tt, 256>>>(kv, wt_h, wt_l);

    // G4: out_pre[b][1024,768] = w^T[b] @ vT[b]^T   (A transposed-read from [t][n])
    gemm3<true><<<dim3(6, 8, Bb), 256, TA_SMEM>>>(
        wt_h, wt_l, vt_h, vt_l, out, nullptr, nullptr,
        Tt, Cc, Nn, (long)Tt*Nn, (long)Cc*Tt, (long)Nn*Cc, nullptr, 1.f);

    // BN2 + final
    bn_partial<<<128, 256>>>(out, p2);
    bn_finalize<<<3, 256>>>(p2, 128, 1.f/(float)ROWS2, mu2, rs2);
    final_apply<<<12288, 256>>>(out, image, g2, b2);
}

// round 5
// speedup vs baseline: 1.0108x; 1.0108x over previous
#include <cuda_runtime.h>
#include <cuda_fp16.h>
#include <cstdint>
#include <math.h>

#define Bb 16
#define Nn 1024
#define Tt 512
#define Cc 768
#define ROWS1 (Bb*Tt)   // 8192
#define ROWS2 (Bb*Nn)   // 16384

typedef unsigned short ushrt;

// ---------------- device scratch ----------------
__device__ float g_y1[(size_t)ROWS1*Cc];        // text@Wc^T (pre-BN)
__device__ float g_attn[(size_t)Bb*Tt*Nn];      // attn_t[B,T,N] fp32
__device__ float g_p1[64*2*Cc];
__device__ float g_p2[128*2*Cc];
__device__ float g_mu1[Cc], g_rs1[Cc], g_mu2[Cc], g_rs2[Cc];

// packed fp16 hi/lo operands, row-major
__device__ ushrt p_text_hi[(size_t)ROWS1*Cc], p_text_lo[(size_t)ROWS1*Cc];
__device__ ushrt p_img_hi [(size_t)ROWS2*Cc], p_img_lo [(size_t)ROWS2*Cc];
__device__ ushrt p_Wc_hi[Cc*Cc], p_Wc_lo[Cc*Cc];
__device__ ushrt p_Wo_hi[Cc*Cc], p_Wo_lo[Cc*Cc];
__device__ ushrt p_e1_hi[(size_t)ROWS1*Cc], p_e1_lo[(size_t)ROWS1*Cc];
__device__ ushrt p_vt_hi[(size_t)Bb*Cc*Tt], p_vt_lo[(size_t)Bb*Cc*Tt];   // vT[b][c][t]
__device__ ushrt p_wt_hi[(size_t)Bb*Tt*Nn], p_wt_lo[(size_t)Bb*Tt*Nn];   // w[b][t][n]

// ---------------- helpers ----------------
__device__ __forceinline__ uint32_t smem_u32(const void* p) {
    uint32_t a;
    asm("{ .reg .u64 t; cvta.to.shared.u64 t, %1; cvt.u32.u64 %0, t; }" : "=r"(a) : "l"(p));
    return a;
}
__device__ __forceinline__ void cpa16(uint32_t d, const void* s) {
    asm volatile("cp.async.cg.shared.global [%0], [%1], 16;" :: "r"(d), "l"(s));
}
__device__ __forceinline__ void cpa_commit() { asm volatile("cp.async.commit_group;" ::: "memory"); }
template<int N> __device__ __forceinline__ void cpa_wait() {
    asm volatile("cp.async.wait_group %0;" :: "n"(N) : "memory");
}
#define LDM4(r, addr) \
    asm volatile("ldmatrix.sync.aligned.m8n8.x4.shared.b16 {%0,%1,%2,%3}, [%4];" \
        : "=r"((r)[0]), "=r"((r)[1]), "=r"((r)[2]), "=r"((r)[3]) : "r"(addr))
#define LDM4T(r, addr) \
    asm volatile("ldmatrix.sync.aligned.m8n8.x4.trans.shared.b16 {%0,%1,%2,%3}, [%4];" \
        : "=r"((r)[0]), "=r"((r)[1]), "=r"((r)[2]), "=r"((r)[3]) : "r"(addr))
#define MMA16816(d, a, b0, b1) \
    asm volatile("mma.sync.aligned.m16n8k16.row.col.f32.f16.f16.f32 " \
        "{%0,%1,%2,%3}, {%4,%5,%6,%7}, {%8,%9}, {%0,%1,%2,%3};" \
        : "+f"((d)[0]), "+f"((d)[1]), "+f"((d)[2]), "+f"((d)[3]) \
        : "r"((a)[0]), "r"((a)[1]), "r"((a)[2]), "r"((a)[3]), "r"(b0), "r"(b1))

__device__ __forceinline__ void split2(float x, ushrt& h, ushrt& l) {
    __half hh = __float2half_rn(x);
    float fh = __half2float(hh);
    __half ll = __float2half_rn(x - fh);
    h = *reinterpret_cast<ushrt*>(&hh);
    l = *reinterpret_cast<ushrt*>(&ll);
}

// GEMM param pack
struct GP {
    const ushrt *Ah, *Al, *Bh, *Bl;
    float* C; ushrt *Ch, *Cl;
    int K, Nc, ldA;
    long sA, sB, sC;
    const float* bias;
    float alpha;
    int gx;            // grid x extent (for dual decode)
};

// ---------------- fp16x3 MMA GEMM body ----------------
// C[M,N] = alpha*(A @ B^T) (+ rowBias[m]).
//  TA=false: A row-major [M][ldA].  TA=true: A stored [K][ldA] K-major, read transposed.
// B row-major [N][K]. BM=BN=128, BK=32, 256 threads, warp tile 64x32.
// 3-stage cp.async pipeline, ONE __syncthreads per chunk.
template<bool TA>
__device__ __forceinline__ void gemm_body(const GP& P, int bx, int by, int bz, char* smem)
{
    constexpr int A_TILE = TA ? 8704 : 10240;    // TA: [32][136] fp16 ; NT: [128][40]
    constexpr int B_TILE = 10240;
    constexpr int STAGE  = 2*A_TILE + 2*B_TILE;
    const int tid = threadIdx.x, wid = tid >> 5, lid = tid & 31;
    const int m0 = by * 128, n0 = bx * 128;
    const int K = P.K, Nc = P.Nc, ldA = P.ldA;
    const int nk = K >> 5;
    const uint32_t sb = smem_u32(smem);

    const ushrt* gAh;
    const ushrt* gAl;
    if constexpr (TA) {
        gAh = P.Ah + (size_t)bz * P.sA + m0;
        gAl = P.Al + (size_t)bz * P.sA + m0;
    } else {
        gAh = P.Ah + (size_t)bz * P.sA + (size_t)m0 * ldA;
        gAl = P.Al + (size_t)bz * P.sA + (size_t)m0 * ldA;
    }
    const ushrt* gBh = P.Bh + (size_t)bz * P.sB + (size_t)n0 * K;
    const ushrt* gBl = P.Bl + (size_t)bz * P.sB + (size_t)n0 * K;

    uint32_t a_sm[2]; size_t a_g[2];
    uint32_t b_sm[2]; size_t b_g[2];
#pragma unroll
    for (int j = 0; j < 2; j++) {
        int i = tid + 256 * j;
        if constexpr (TA) {
            int r = i >> 4, c8 = (i & 15) * 8;          // 32 rows x 128 cols
            a_sm[j] = (uint32_t)(r * 272 + c8 * 2);
            a_g[j]  = (size_t)r * ldA + c8;
        } else {
            int r = i >> 2, c8 = (i & 3) * 8;           // 128 rows x 32 cols
            a_sm[j] = (uint32_t)(r * 80 + c8 * 2);
            a_g[j]  = (size_t)r * ldA + c8;
        }
        int r = i >> 2, c8 = (i & 3) * 8;
        b_sm[j] = (uint32_t)(r * 80 + c8 * 2);
        b_g[j]  = (size_t)r * K + c8;
    }

    auto load_chunk = [&](int c, int s) {
        uint32_t ds = sb + (uint32_t)s * STAGE;
        size_t aoff = TA ? (size_t)c * 32 * ldA : (size_t)c * 32;
        size_t boff = (size_t)c * 32;
#pragma unroll
        for (int j = 0; j < 2; j++) {
            cpa16(ds + a_sm[j],              gAh + aoff + a_g[j]);
            cpa16(ds + A_TILE + a_sm[j],     gAl + aoff + a_g[j]);
            cpa16(ds + 2*A_TILE + b_sm[j],          gBh + boff + b_g[j]);
            cpa16(ds + 2*A_TILE + B_TILE + b_sm[j], gBl + boff + b_g[j]);
        }
    };

    const int wm0 = (wid >> 2) * 64, wn0 = (wid & 3) * 32;
    uint32_t a_fb;
    if constexpr (TA) {
        int k_off = (lid & 7) + ((lid >> 4) << 3);
        int m_off = ((lid >> 3) & 1) << 3;
        a_fb = (uint32_t)(k_off * 272 + (wm0 + m_off) * 2);
    } else {
        a_fb = (uint32_t)(((wm0 + (lid & 15)) * 40 + (lid >> 4) * 8) * 2);
    }
    const uint32_t b_fb = (uint32_t)(2*A_TILE + ((wn0 + (lid & 15)) * 40 + (lid >> 4) * 8) * 2);

    float acc[4][4][4] = {};

    load_chunk(0, 0);
    cpa_commit();
    load_chunk(1, 1);
    cpa_commit();

    int s_next = 2;
    for (int c = 0; c < nk; c++) {
        cpa_wait<1>();
        __syncthreads();                       // single barrier per chunk
        if (c + 2 < nk) load_chunk(c + 2, s_next);
        cpa_commit();
        s_next = (s_next == 2) ? 0 : s_next + 1;

        const uint32_t st = sb + (uint32_t)(c % 3) * STAGE;
#pragma unroll
        for (int kk = 0; kk < 2; kk++) {
            uint32_t Ahf[4][4], Alf[4][4], Bhf[2][4], Blf[2][4];
            if constexpr (TA) {
                const uint32_t ak = st + a_fb + kk * 4352;     // kk*16 rows * 272B
#pragma unroll
                for (int mi = 0; mi < 4; mi++) {
                    LDM4T(Ahf[mi], ak + mi * 32);
                    LDM4T(Alf[mi], ak + A_TILE + mi * 32);
                }
            } else {
                const uint32_t ak = st + a_fb + kk * 32;
#pragma unroll
                for (int mi = 0; mi < 4; mi++) {
                    LDM4(Ahf[mi], ak + mi * 1280);
                    LDM4(Alf[mi], ak + A_TILE + mi * 1280);
                }
            }
            const uint32_t bk = st + b_fb + kk * 32;
#pragma unroll
            for (int p = 0; p < 2; p++) {
                LDM4(Bhf[p], bk + p * 1280);
                LDM4(Blf[p], bk + B_TILE + p * 1280);
            }
#pragma unroll
            for (int mi = 0; mi < 4; mi++) {
#pragma unroll
                for (int nj = 0; nj < 4; nj++) {
                    const int p = nj >> 1, h = nj & 1;
                    MMA16816(acc[mi][nj], Ahf[mi], Bhf[p][h], Bhf[p][h + 2]);
                    MMA16816(acc[mi][nj], Ahf[mi], Blf[p][h], Blf[p][h + 2]);
                    MMA16816(acc[mi][nj], Alf[mi], Bhf[p][h], Bhf[p][h + 2]);
                }
            }
        }
    }

    // epilogue (registers only; no smem reuse -> no barrier needed)
    const int qr = lid >> 2, qc = (lid & 3) * 2;
#pragma unroll
    for (int mi = 0; mi < 4; mi++) {
        const int row0 = m0 + wm0 + mi * 16 + qr;
        const int row1 = row0 + 8;
        const float bv0 = P.bias ? P.bias[row0] : 0.f;
        const float bv1 = P.bias ? P.bias[row1] : 0.f;
#pragma unroll
        for (int nj = 0; nj < 4; nj++) {
            const int col = n0 + wn0 + nj * 8 + qc;
            float v00 = acc[mi][nj][0] * P.alpha + bv0;
            float v01 = acc[mi][nj][1] * P.alpha + bv0;
            float v10 = acc[mi][nj][2] * P.alpha + bv1;
            float v11 = acc[mi][nj][3] * P.alpha + bv1;
            if (P.Ch) {
                ushort2 h0, l0, h1, l1;
                split2(v00, h0.x, l0.x); split2(v01, h0.y, l0.y);
                split2(v10, h1.x, l1.x); split2(v11, h1.y, l1.y);
                size_t o0 = (size_t)bz * P.sC + (size_t)row0 * Nc + col;
                size_t o1 = (size_t)bz * P.sC + (size_t)row1 * Nc + col;
                *reinterpret_cast<ushort2*>(P.Ch + o0) = h0;
                *reinterpret_cast<ushort2*>(P.Cl + o0) = l0;
                *reinterpret_cast<ushort2*>(P.Ch + o1) = h1;
                *reinterpret_cast<ushort2*>(P.Cl + o1) = l1;
            } else {
                float* Cb = P.C + (size_t)bz * P.sC;
                float2 a0, a1;
                a0.x = v00; a0.y = v01; a1.x = v10; a1.y = v11;
                *reinterpret_cast<float2*>(Cb + (size_t)row0 * Nc + col) = a0;
                *reinterpret_cast<float2*>(Cb + (size_t)row1 * Nc + col) = a1;
            }
        }
    }
}

#define NT_SMEM (3*(2*10240 + 2*10240))   // 122880
#define TA_SMEM (3*(2*8704  + 2*10240))   // 113664

__global__ void __launch_bounds__(256, 1) gemm_nt(GP P) {
    extern __shared__ __align__(16) char smem[];
    gemm_body<false>(P, blockIdx.x, blockIdx.y, blockIdx.z, smem);
}
__global__ void __launch_bounds__(256, 1) gemm_ta(GP P) {
    extern __shared__ __align__(16) char smem[];
    gemm_body<true>(P, blockIdx.x, blockIdx.y, blockIdx.z, smem);
}
// two independent NT GEMMs fused into one launch (fills wave tail)
__global__ void __launch_bounds__(256, 1) gemm_dual(GP P1, GP P2, int n1, int gy2) {
    extern __shared__ __align__(16) char smem[];
    int id = blockIdx.x;
    if (id < n1) {
        gemm_body<false>(P1, id % P1.gx, id / P1.gx, 0, smem);
    } else {
        id -= n1;
        int bx = id % P2.gx;
        int r  = id / P2.gx;
        gemm_body<false>(P2, bx, r % gy2, r / gy2, smem);
    }
}

// ---------------- pack kernels ----------------
__global__ __launch_bounds__(256) void pack_split(const float4* __restrict__ X,
                                                  ushort4* __restrict__ H, ushort4* __restrict__ L, long n4)
{
    long i = (long)blockIdx.x * 256 + threadIdx.x;
    if (i >= n4) return;
    float4 v = X[i];
    ushort4 h, l;
    split2(v.x, h.x, l.x); split2(v.y, h.y, l.y);
    split2(v.z, h.z, l.z); split2(v.w, h.w, l.w);
    H[i] = h; L[i] = l;
}

__global__ __launch_bounds__(256) void pack_bn_relu(const float4* __restrict__ X,
                                                    ushort4* __restrict__ H, ushort4* __restrict__ L,
                                                    const float* __restrict__ g, const float* __restrict__ bb)
{
    long i = (long)blockIdx.x * 256 + threadIdx.x;   // over ROWS1*Cc/4
    float4 v = X[i];
    int ch = (int)((i * 4) % Cc);
    v.x = fmaxf(g[ch+0]*(v.x - g_mu1[ch+0])*g_rs1[ch+0] + bb[ch+0], 0.f);
    v.y = fmaxf(g[ch+1]*(v.y - g_mu1[ch+1])*g_rs1[ch+1] + bb[ch+1], 0.f);
    v.z = fmaxf(g[ch+2]*(v.z - g_mu1[ch+2])*g_rs1[ch+2] + bb[ch+2], 0.f);
    v.w = fmaxf(g[ch+3]*(v.w - g_mu1[ch+3])*g_rs1[ch+3] + bb[ch+3], 0.f);
    ushort4 h, l;
    split2(v.x, h.x, l.x); split2(v.y, h.y, l.y);
    split2(v.z, h.z, l.z); split2(v.w, h.w, l.w);
    H[i] = h; L[i] = l;
}

// ---------------- per-(b,t) column: softmax + K-th-largest radix select -> fp16 hi/lo ----------------
__global__ __launch_bounds__(256) void topk_softmax(const float* __restrict__ kvals,
                                                    ushrt* __restrict__ Wh, ushrt* __restrict__ Wl)
{
    const int b = blockIdx.x >> 9;
    const int t = blockIdx.x & 511;
    const size_t base = ((size_t)b * Tt + t) * Nn;
    const float* col = g_attn + base;
    const int tid = threadIdx.x;
    __shared__ float sh[8];
    __shared__ unsigned hist[256];
    __shared__ unsigned s_sel, s_rem;

    float x[4]; unsigned u[4];
    float mx = -3.4e38f;
#pragma unroll
    for (int i = 0; i < 4; i++) {
        x[i] = col[tid + 256 * i];
        mx = fmaxf(mx, x[i]);
        unsigned bits = __float_as_uint(x[i]);
        u[i] = (bits & 0x80000000u) ? ~bits : (bits | 0x80000000u);
    }
    for (int o = 16; o > 0; o >>= 1) mx = fmaxf(mx, __shfl_xor_sync(0xffffffffu, mx, o));
    if ((tid & 31) == 0) sh[tid >> 5] = mx;
    __syncthreads();
    if (tid == 0) { float m = sh[0]; for (int i = 1; i < 8; i++) m = fmaxf(m, sh[i]); sh[0] = m; }
    __syncthreads();
    mx = sh[0];
    __syncthreads();
    float s = 0.f;
#pragma unroll
    for (int i = 0; i < 4; i++) s += expf(x[i] - mx);
    for (int o = 16; o > 0; o >>= 1) s += __shfl_xor_sync(0xffffffffu, s, o);
    if ((tid & 31) == 0) sh[tid >> 5] = s;
    __syncthreads();
    if (tid == 0) { float m = 0.f; for (int i = 0; i < 8; i++) m += sh[i]; sh[0] = m; }
    __syncthreads();
    const float inv = 1.f / sh[0];

    int K = (int)rintf((float)Nn * kvals[b]);
    if (K < 0) K = 0;
    if (K > Nn) K = Nn;
    if (K == 0) {
#pragma unroll
        for (int i = 0; i < 4; i++) { Wh[base + tid + 256*i] = 0; Wl[base + tid + 256*i] = 0; }
        return;
    }
    unsigned thr = 0u;
    if (K < Nn) {
        unsigned pref = 0u, rem = (unsigned)K;
        for (int shift = 24; shift >= 0; shift -= 8) {
            hist[tid] = 0u;
            __syncthreads();
            unsigned hm = (shift == 24) ? 0u : (0xFFFFFFFFu << (shift + 8));
#pragma unroll
            for (int i = 0; i < 4; i++)
                if ((u[i] & hm) == pref) atomicAdd(&hist[(u[i] >> shift) & 255u], 1u);
            __syncthreads();
            for (int off = 1; off < 256; off <<= 1) {
                unsigned vv = (tid + off < 256) ? hist[tid + off] : 0u;
                __syncthreads();
                hist[tid] += vv;
                __syncthreads();
            }
            unsigned nxt = (tid < 255) ? hist[tid + 1] : 0u;
            if (hist[tid] >= rem && nxt < rem) { s_sel = (unsigned)tid; s_rem = rem - nxt; }
            __syncthreads();
            pref |= (s_sel << shift);
            rem = s_rem;
            __syncthreads();
        }
        thr = pref;
    }
#pragma unroll
    for (int i = 0; i < 4; i++) {
        float w = (u[i] >= thr) ? expf(x[i] - mx) * inv : 0.f;
        ushrt h, l;
        split2(w, h, l);
        Wh[base + tid + 256*i] = h;
        Wl[base + tid + 256*i] = l;
    }
}

// ---------------- BN stats ----------------
__global__ __launch_bounds__(256) void bn_partial(const float* __restrict__ X, float* __restrict__ part)
{
    const int tid = threadIdx.x;
    const float* base = X + (size_t)blockIdx.x * 128 * Cc;
    float s0=0,s1=0,s2=0,q0=0,q1=0,q2=0;
    for (int r = 0; r < 128; r++) {
        const float* row = base + (size_t)r * Cc;
        float a = row[tid], b = row[tid+256], c = row[tid+512];
        s0 += a; q0 = fmaf(a,a,q0);
        s1 += b; q1 = fmaf(b,b,q1);
        s2 += c; q2 = fmaf(c,c,q2);
    }
    float* p = part + (size_t)blockIdx.x * (2*Cc);
    p[tid]    = s0; p[tid+256]    = s1; p[tid+512]    = s2;
    p[Cc+tid] = q0; p[Cc+tid+256] = q1; p[Cc+tid+512] = q2;
}

__global__ void bn_finalize(const float* __restrict__ part, int nblk, float invN,
                            float* __restrict__ mu, float* __restrict__ rs)
{
    int c = blockIdx.x * 256 + threadIdx.x;
    if (c >= Cc) return;
    float s = 0.f, q = 0.f;
    for (int i = 0; i < nblk; i++) {
        s += part[(size_t)i * 2 * Cc + c];
        q += part[(size_t)i * 2 * Cc + Cc + c];
    }
    float m = s * invN;
    mu[c] = m;
    rs[c] = rsqrtf(q * invN - m * m + 1e-5f);
}

__global__ __launch_bounds__(256) void final_apply(float* __restrict__ out, const float* __restrict__ img,
                                                   const float* __restrict__ g, const float* __restrict__ bb)
{
    int i4 = blockIdx.x * 256 + threadIdx.x;
    float4 o = reinterpret_cast<float4*>(out)[i4];
    float4 im = reinterpret_cast<const float4*>(img)[i4];
    int c = (i4 * 4) % Cc;
    o.x = fmaxf(g[c+0]*(o.x - g_mu2[c+0])*g_rs2[c+0] + bb[c+0], 0.f) + im.x;
    o.y = fmaxf(g[c+1]*(o.y - g_mu2[c+1])*g_rs2[c+1] + bb[c+1], 0.f) + im.y;
    o.z = fmaxf(g[c+2]*(o.z - g_mu2[c+2])*g_rs2[c+2] + bb[c+2], 0.f) + im.z;
    o.w = fmaxf(g[c+3]*(o.w - g_mu2[c+3])*g_rs2[c+3] + bb[c+3], 0.f) + im.w;
    reinterpret_cast<float4*>(out)[i4] = o;
}

// ---------------- orchestration ----------------
extern "C" void kernel_launch(void* const* d_in, const int* in_sizes, int n_in,
                              void* d_out, int out_size)
{
    (void)in_sizes; (void)n_in; (void)out_size;
    const float* image = (const float*)d_in[0];
    const float* text  = (const float*)d_in[1];
    const float* kv    = (const float*)d_in[2];
    const float* Wc    = (const float*)d_in[3];
    const float* g1    = (const float*)d_in[5];
    const float* b1    = (const float*)d_in[6];
    const float* Wout  = (const float*)d_in[7];
    const float* bout  = (const float*)d_in[8];
    const float* g2    = (const float*)d_in[9];
    const float* b2    = (const float*)d_in[10];
    float* out = (float*)d_out;

    float *y1, *attn, *p1, *p2, *mu1, *rs1, *mu2, *rs2;
    ushrt *tx_h, *tx_l, *im_h, *im_l, *wc_h, *wc_l, *wo_h, *wo_l,
          *e1_h, *e1_l, *vt_h, *vt_l, *wt_h, *wt_l;
    cudaGetSymbolAddress((void**)&y1,   g_y1);
    cudaGetSymbolAddress((void**)&attn, g_attn);
    cudaGetSymbolAddress((void**)&p1,   g_p1);
    cudaGetSymbolAddress((void**)&p2,   g_p2);
    cudaGetSymbolAddress((void**)&mu1,  g_mu1);
    cudaGetSymbolAddress((void**)&rs1,  g_rs1);
    cudaGetSymbolAddress((void**)&mu2,  g_mu2);
    cudaGetSymbolAddress((void**)&rs2,  g_rs2);
    cudaGetSymbolAddress((void**)&tx_h, p_text_hi); cudaGetSymbolAddress((void**)&tx_l, p_text_lo);
    cudaGetSymbolAddress((void**)&im_h, p_img_hi);  cudaGetSymbolAddress((void**)&im_l, p_img_lo);
    cudaGetSymbolAddress((void**)&wc_h, p_Wc_hi);   cudaGetSymbolAddress((void**)&wc_l, p_Wc_lo);
    cudaGetSymbolAddress((void**)&wo_h, p_Wo_hi);   cudaGetSymbolAddress((void**)&wo_l, p_Wo_lo);
    cudaGetSymbolAddress((void**)&e1_h, p_e1_hi);   cudaGetSymbolAddress((void**)&e1_l, p_e1_lo);
    cudaGetSymbolAddress((void**)&vt_h, p_vt_hi);   cudaGetSymbolAddress((void**)&vt_l, p_vt_lo);
    cudaGetSymbolAddress((void**)&wt_h, p_wt_hi);   cudaGetSymbolAddress((void**)&wt_l, p_wt_lo);

    cudaFuncSetAttribute(gemm_nt,   cudaFuncAttributeMaxDynamicSharedMemorySize, NT_SMEM);
    cudaFuncSetAttribute(gemm_ta,   cudaFuncAttributeMaxDynamicSharedMemorySize, TA_SMEM);
    cudaFuncSetAttribute(gemm_dual, cudaFuncAttributeMaxDynamicSharedMemorySize, NT_SMEM);

    const float inv_sqrtC = 0.03608439182435161f;  // 1/sqrt(768)

    // pack fp32 -> fp16 hi/lo
    pack_split<<<6144, 256>>>((const float4*)text,  (ushort4*)tx_h, (ushort4*)tx_l, (long)ROWS1*Cc/4);
    pack_split<<<12288, 256>>>((const float4*)image, (ushort4*)im_h, (ushort4*)im_l, (long)ROWS2*Cc/4);
    pack_split<<<576, 256>>>((const float4*)Wc,   (ushort4*)wc_h, (ushort4*)wc_l, (long)Cc*Cc/4);
    pack_split<<<576, 256>>>((const float4*)Wout, (ushort4*)wo_h, (ushort4*)wo_l, (long)Cc*Cc/4);

    // G1: y1[8192,768] = text @ Wc^T  (bias bc cancels inside BN1)
    GP P1 = { tx_h, tx_l, wc_h, wc_l, y1, nullptr, nullptr,
              Cc, Cc, Cc, 0, 0, 0, nullptr, 1.f, 6 };
    // G2: vT[b][768,512] = Wout @ text[b]^T + bout[row] -> fp16 hi/lo directly
    GP P2 = { wo_h, wo_l, tx_h, tx_l, nullptr, vt_h, vt_l,
              Cc, Tt, Cc, 0, (long)Tt*Cc, (long)Cc*Tt, bout, 1.f, 4 };
    gemm_dual<<<384 + 384, 256, NT_SMEM>>>(P1, P2, 384, 6);

    // BN1 stats + fused BN+relu+split-pack of e1
    bn_partial<<<64, 256>>>(y1, p1);
    bn_finalize<<<3, 256>>>(p1, 64, 1.f/(float)ROWS1, mu1, rs1);
    pack_bn_relu<<<6144, 256>>>((const float4*)y1, (ushort4*)e1_h, (ushort4*)e1_l, g1, b1);

    // G3: attn_t[b][512,1024] = (e1[b] @ image[b]^T) / sqrt(C)
    GP P3 = { e1_h, e1_l, im_h, im_l, attn, nullptr, nullptr,
              Cc, Nn, Cc, (long)Tt*Cc, (long)Nn*Cc, (long)Tt*Nn, nullptr, inv_sqrtC, 8 };
    gemm_nt<<<dim3(8, 4, Bb), 256, NT_SMEM>>>(P3);

    // masked softmax weights -> fp16 hi/lo in [b][t][n] layout
    topk_softmax<<<Bb*Tt, 256>>>(kv, wt_h, wt_l);

    // G4: out_pre[b][1024,768] = w^T[b] @ vT[b]^T  (A transposed-read from [t][n])
    GP P4 = { wt_h, wt_l, vt_h, vt_l, out, nullptr, nullptr,
              Tt, Cc, Nn, (long)Tt*Nn, (long)Cc*Tt, (long)Nn*Cc, nullptr, 1.f, 6 };
    gemm_ta<<<dim3(6, 8, Bb), 256, TA_SMEM>>>(P4);

    // BN2 + final
    bn_partial<<<128, 256>>>(out, p2);
    bn_finalize<<<3, 256>>>(p2, 128, 1.f/(float)ROWS2, mu2, rs2);
    final_apply<<<12288, 256>>>(out, image, g2, b2);
}

// round 6
// speedup vs baseline: 1.0383x; 1.0272x over previous
#include <cuda_runtime.h>
#include <cuda_fp16.h>
#include <cstdint>
#include <math.h>

#define Bb 16
#define Nn 1024
#define Tt 512
#define Cc 768
#define ROWS1 (Bb*Tt)   // 8192
#define ROWS2 (Bb*Nn)   // 16384

typedef unsigned short ushrt;

// ---------------- device scratch ----------------
__device__ float g_y1[(size_t)ROWS1*Cc];        // text@Wc^T (pre-BN)
__device__ float g_attn[(size_t)Bb*Tt*Nn];      // attn_t[B,T,N] fp32
__device__ float g_p1[64*2*Cc];
__device__ float g_p2[128*2*Cc];
__device__ float g_mu1[Cc], g_rs1[Cc], g_mu2[Cc], g_rs2[Cc];

// packed fp16 hi/lo operands
__device__ ushrt p_text_hi[(size_t)ROWS1*Cc], p_text_lo[(size_t)ROWS1*Cc];
__device__ ushrt p_img_hi [(size_t)ROWS2*Cc], p_img_lo [(size_t)ROWS2*Cc];
__device__ ushrt p_Wcat_hi[2*Cc*Cc], p_Wcat_lo[2*Cc*Cc];                 // [Wc; Wout] rows
__device__ ushrt p_e1_hi[(size_t)ROWS1*Cc], p_e1_lo[(size_t)ROWS1*Cc];
__device__ ushrt p_v_hi[(size_t)ROWS1*Cc],  p_v_lo[(size_t)ROWS1*Cc];    // v[b][t][c]
__device__ ushrt p_wt_hi[(size_t)Bb*Tt*Nn], p_wt_lo[(size_t)Bb*Tt*Nn];   // w[b][t][n]

// ---------------- helpers ----------------
__device__ __forceinline__ uint32_t smem_u32(const void* p) {
    uint32_t a;
    asm("{ .reg .u64 t; cvta.to.shared.u64 t, %1; cvt.u32.u64 %0, t; }" : "=r"(a) : "l"(p));
    return a;
}
__device__ __forceinline__ void cpa16(uint32_t d, const void* s) {
    asm volatile("cp.async.cg.shared.global [%0], [%1], 16;" :: "r"(d), "l"(s));
}
__device__ __forceinline__ void cpa_commit() { asm volatile("cp.async.commit_group;" ::: "memory"); }
template<int N> __device__ __forceinline__ void cpa_wait() {
    asm volatile("cp.async.wait_group %0;" :: "n"(N) : "memory");
}
#define LDM4(r, addr) \
    asm volatile("ldmatrix.sync.aligned.m8n8.x4.shared.b16 {%0,%1,%2,%3}, [%4];" \
        : "=r"((r)[0]), "=r"((r)[1]), "=r"((r)[2]), "=r"((r)[3]) : "r"(addr))
#define LDM4T(r, addr) \
    asm volatile("ldmatrix.sync.aligned.m8n8.x4.trans.shared.b16 {%0,%1,%2,%3}, [%4];" \
        : "=r"((r)[0]), "=r"((r)[1]), "=r"((r)[2]), "=r"((r)[3]) : "r"(addr))
#define MMA16816(d, a, b0, b1) \
    asm volatile("mma.sync.aligned.m16n8k16.row.col.f32.f16.f16.f32 " \
        "{%0,%1,%2,%3}, {%4,%5,%6,%7}, {%8,%9}, {%0,%1,%2,%3};" \
        : "+f"((d)[0]), "+f"((d)[1]), "+f"((d)[2]), "+f"((d)[3]) \
        : "r"((a)[0]), "r"((a)[1]), "r"((a)[2]), "r"((a)[3]), "r"(b0), "r"(b1))

__device__ __forceinline__ void split2(float x, ushrt& h, ushrt& l) {
    __half hh = __float2half_rn(x);
    float fh = __half2float(hh);
    __half ll = __float2half_rn(x - fh);
    h = *reinterpret_cast<ushrt*>(&hh);
    l = *reinterpret_cast<ushrt*>(&ll);
}

struct GP {
    const ushrt *Ah, *Al, *Bh, *Bl;
    float* C; ushrt *Ch, *Cl;          // fp32 out, or split-fp16 out region (vmode)
    int K, Nc, ldA, ldB;
    long sA, sB, sC;
    const float* bias;                 // column bias, vmode only
    float alpha;
    int nsplit;                        // n0 >= nsplit -> vmode split output
};

// ---------------- fp16x3 MMA GEMM body ----------------
// CTA tile 128(M) x 64(N), BK=32, 128 threads (4 warps 2x2), warp tile 64x32.
// TN=false: A row-major [M][ldA], B row-major [N][ldB].
// TN=true:  A K-major [K][ldA], B K-major [K][ldB] (both trans-loaded).
// 3-stage cp.async pipeline, one __syncthreads per chunk.
template<bool TN>
__device__ __forceinline__ void gemm_body(const GP& P, int bx, int by, int bz, char* smem)
{
    constexpr int A_TILE = TN ? 8704 : 10240;   // TN: [32][136]; NT: [128][40]
    constexpr int B_TILE = TN ? 4608 : 5120;    // TN: [32][72];  NT: [64][40]
    constexpr int STAGE  = 2*A_TILE + 2*B_TILE;
    const int tid = threadIdx.x, wid = tid >> 5, lid = tid & 31;
    const int m0 = by * 128, n0 = bx * 64;
    const int K = P.K, nk = K >> 5, ldA = P.ldA, ldB = P.ldB;
    const uint32_t sb = smem_u32(smem);

    const ushrt *gAh, *gAl, *gBh, *gBl;
    if constexpr (TN) {
        gAh = P.Ah + (size_t)bz * P.sA + m0;
        gAl = P.Al + (size_t)bz * P.sA + m0;
        gBh = P.Bh + (size_t)bz * P.sB + n0;
        gBl = P.Bl + (size_t)bz * P.sB + n0;
    } else {
        gAh = P.Ah + (size_t)bz * P.sA + (size_t)m0 * ldA;
        gAl = P.Al + (size_t)bz * P.sA + (size_t)m0 * ldA;
        gBh = P.Bh + (size_t)bz * P.sB + (size_t)n0 * ldB;
        gBl = P.Bl + (size_t)bz * P.sB + (size_t)n0 * ldB;
    }

    uint32_t a_sm[4]; size_t a_g[4];
    uint32_t b_sm[2]; size_t b_g[2];
#pragma unroll
    for (int j = 0; j < 4; j++) {
        int i = tid + 128 * j;
        if constexpr (TN) { int r = i >> 4, c8 = (i & 15) * 8; a_sm[j] = (uint32_t)(r * 272 + c8 * 2); a_g[j] = (size_t)r * ldA + c8; }
        else              { int r = i >> 2, c8 = (i & 3) * 8;  a_sm[j] = (uint32_t)(r * 80 + c8 * 2);  a_g[j] = (size_t)r * ldA + c8; }
    }
#pragma unroll
    for (int j = 0; j < 2; j++) {
        int i = tid + 128 * j;
        if constexpr (TN) { int r = i >> 3, c8 = (i & 7) * 8; b_sm[j] = (uint32_t)(r * 144 + c8 * 2); b_g[j] = (size_t)r * ldB + c8; }
        else              { int r = i >> 2, c8 = (i & 3) * 8; b_sm[j] = (uint32_t)(r * 80 + c8 * 2);  b_g[j] = (size_t)r * ldB + c8; }
    }

    auto load_chunk = [&](int c, int s) {
        uint32_t ds = sb + (uint32_t)s * STAGE;
        size_t aoff = TN ? (size_t)c * 32 * ldA : (size_t)c * 32;
        size_t boff = TN ? (size_t)c * 32 * ldB : (size_t)c * 32;
#pragma unroll
        for (int j = 0; j < 4; j++) {
            cpa16(ds + a_sm[j],          gAh + aoff + a_g[j]);
            cpa16(ds + A_TILE + a_sm[j], gAl + aoff + a_g[j]);
        }
#pragma unroll
        for (int j = 0; j < 2; j++) {
            cpa16(ds + 2*A_TILE + b_sm[j],          gBh + boff + b_g[j]);
            cpa16(ds + 2*A_TILE + B_TILE + b_sm[j], gBl + boff + b_g[j]);
        }
    };

    const int wm0 = (wid >> 1) * 64, wn0 = (wid & 1) * 32;
    uint32_t a_fb, b_fb;
    if constexpr (TN) {
        int k_off = (lid & 7) + ((lid >> 4) << 3);
        int x_off = ((lid >> 3) & 1) << 3;
        a_fb = (uint32_t)(k_off * 272 + (wm0 + x_off) * 2);
        b_fb = (uint32_t)(2*A_TILE + k_off * 144 + (wn0 + x_off) * 2);
    } else {
        a_fb = (uint32_t)(((wm0 + (lid & 15)) * 40 + (lid >> 4) * 8) * 2);
        b_fb = (uint32_t)(2*A_TILE + ((wn0 + (lid & 15)) * 40 + (lid >> 4) * 8) * 2);
    }

    float acc[4][4][4] = {};

    load_chunk(0, 0);
    cpa_commit();
    load_chunk(1, 1);
    cpa_commit();

    int s_next = 2;
    for (int c = 0; c < nk; c++) {
        cpa_wait<1>();
        __syncthreads();
        if (c + 2 < nk) load_chunk(c + 2, s_next);
        cpa_commit();
        s_next = (s_next == 2) ? 0 : s_next + 1;

        const uint32_t st = sb + (uint32_t)(c % 3) * STAGE;
#pragma unroll
        for (int kk = 0; kk < 2; kk++) {
            uint32_t Ahf[4][4], Alf[4][4], Bhf[2][4], Blf[2][4];
            if constexpr (TN) {
                const uint32_t ak = st + a_fb + kk * 4352;     // 16 k-rows * 272B
                const uint32_t bk = st + b_fb + kk * 2304;     // 16 k-rows * 144B
#pragma unroll
                for (int mi = 0; mi < 4; mi++) {
                    LDM4T(Ahf[mi], ak + mi * 32);
                    LDM4T(Alf[mi], ak + A_TILE + mi * 32);
                }
#pragma unroll
                for (int p = 0; p < 2; p++) {
                    LDM4T(Bhf[p], bk + p * 32);
                    LDM4T(Blf[p], bk + B_TILE + p * 32);
                }
            } else {
                const uint32_t ak = st + a_fb + kk * 32;
                const uint32_t bk = st + b_fb + kk * 32;
#pragma unroll
                for (int mi = 0; mi < 4; mi++) {
                    LDM4(Ahf[mi], ak + mi * 1280);
                    LDM4(Alf[mi], ak + A_TILE + mi * 1280);
                }
#pragma unroll
                for (int p = 0; p < 2; p++) {
                    LDM4(Bhf[p], bk + p * 1280);
                    LDM4(Blf[p], bk + B_TILE + p * 1280);
                }
            }
            // products outermost: 16-MMA spacing between same-acc RAW
#pragma unroll
            for (int mi = 0; mi < 4; mi++)
#pragma unroll
                for (int nj = 0; nj < 4; nj++)
                    MMA16816(acc[mi][nj], Ahf[mi], Bhf[nj>>1][nj&1], Bhf[nj>>1][(nj&1)+2]);
#pragma unroll
            for (int mi = 0; mi < 4; mi++)
#pragma unroll
                for (int nj = 0; nj < 4; nj++)
                    MMA16816(acc[mi][nj], Ahf[mi], Blf[nj>>1][nj&1], Blf[nj>>1][(nj&1)+2]);
#pragma unroll
            for (int mi = 0; mi < 4; mi++)
#pragma unroll
                for (int nj = 0; nj < 4; nj++)
                    MMA16816(acc[mi][nj], Alf[mi], Bhf[nj>>1][nj&1], Bhf[nj>>1][(nj&1)+2]);
        }
    }

    // epilogue
    const int qr = lid >> 2, qc = (lid & 3) * 2;
    const bool vmode = (n0 >= P.nsplit);
#pragma unroll
    for (int mi = 0; mi < 4; mi++) {
        const int row0 = m0 + wm0 + mi * 16 + qr;
        const int row1 = row0 + 8;
#pragma unroll
        for (int nj = 0; nj < 4; nj++) {
            const int col = n0 + wn0 + nj * 8 + qc;
            float v00 = acc[mi][nj][0] * P.alpha;
            float v01 = acc[mi][nj][1] * P.alpha;
            float v10 = acc[mi][nj][2] * P.alpha;
            float v11 = acc[mi][nj][3] * P.alpha;
            if (vmode) {
                const int c0 = col - P.nsplit;
                if (P.bias) {
                    float b0 = P.bias[c0], b1 = P.bias[c0 + 1];
                    v00 += b0; v01 += b1; v10 += b0; v11 += b1;
                }
                ushort2 h0, l0, h1, l1;
                split2(v00, h0.x, l0.x); split2(v01, h0.y, l0.y);
                split2(v10, h1.x, l1.x); split2(v11, h1.y, l1.y);
                size_t o0 = (size_t)row0 * P.Nc + c0;
                size_t o1 = (size_t)row1 * P.Nc + c0;
                *reinterpret_cast<ushort2*>(P.Ch + o0) = h0;
                *reinterpret_cast<ushort2*>(P.Cl + o0) = l0;
                *reinterpret_cast<ushort2*>(P.Ch + o1) = h1;
                *reinterpret_cast<ushort2*>(P.Cl + o1) = l1;
            } else {
                float* Cb = P.C + (size_t)bz * P.sC;
                float2 a0, a1;
                a0.x = v00; a0.y = v01; a1.x = v10; a1.y = v11;
                *reinterpret_cast<float2*>(Cb + (size_t)row0 * P.Nc + col) = a0;
                *reinterpret_cast<float2*>(Cb + (size_t)row1 * P.Nc + col) = a1;
            }
        }
    }
}

#define NT_SMEM (3*(2*10240 + 2*5120))   // 92160
#define TN_SMEM (3*(2*8704  + 2*4608))   // 79872

__global__ void __launch_bounds__(128, 2) gemm_nt(GP P) {
    extern __shared__ __align__(16) char smem[];
    gemm_body<false>(P, blockIdx.x, blockIdx.y, blockIdx.z, smem);
}
__global__ void __launch_bounds__(128, 2) gemm_tn(GP P) {
    extern __shared__ __align__(16) char smem[];
    gemm_body<true>(P, blockIdx.x, blockIdx.y, blockIdx.z, smem);
}

// ---------------- pack kernels ----------------
__global__ __launch_bounds__(256) void pack_weights(const float4* __restrict__ Wc,
                                                    const float4* __restrict__ Wo,
                                                    ushort4* __restrict__ H, ushort4* __restrict__ L)
{
    const long half = (long)Cc * Cc / 4;
    long i = (long)blockIdx.x * 256 + threadIdx.x;
    if (i >= 2 * half) return;
    float4 v = (i < half) ? Wc[i] : Wo[i - half];
    ushort4 h, l;
    split2(v.x, h.x, l.x); split2(v.y, h.y, l.y);
    split2(v.z, h.z, l.z); split2(v.w, h.w, l.w);
    H[i] = h; L[i] = l;
}

__global__ __launch_bounds__(256) void pack_split(const float4* __restrict__ X,
                                                  ushort4* __restrict__ H, ushort4* __restrict__ L, long n4)
{
    long i = (long)blockIdx.x * 256 + threadIdx.x;
    if (i >= n4) return;
    float4 v = X[i];
    ushort4 h, l;
    split2(v.x, h.x, l.x); split2(v.y, h.y, l.y);
    split2(v.z, h.z, l.z); split2(v.w, h.w, l.w);
    H[i] = h; L[i] = l;
}

__global__ __launch_bounds__(256) void pack_bn_relu(const float4* __restrict__ X,
                                                    ushort4* __restrict__ H, ushort4* __restrict__ L,
                                                    const float* __restrict__ g, const float* __restrict__ bb)
{
    long i = (long)blockIdx.x * 256 + threadIdx.x;   // over ROWS1*Cc/4
    float4 v = X[i];
    int ch = (int)((i * 4) % Cc);
    v.x = fmaxf(g[ch+0]*(v.x - g_mu1[ch+0])*g_rs1[ch+0] + bb[ch+0], 0.f);
    v.y = fmaxf(g[ch+1]*(v.y - g_mu1[ch+1])*g_rs1[ch+1] + bb[ch+1], 0.f);
    v.z = fmaxf(g[ch+2]*(v.z - g_mu1[ch+2])*g_rs1[ch+2] + bb[ch+2], 0.f);
    v.w = fmaxf(g[ch+3]*(v.w - g_mu1[ch+3])*g_rs1[ch+3] + bb[ch+3], 0.f);
    ushort4 h, l;
    split2(v.x, h.x, l.x); split2(v.y, h.y, l.y);
    split2(v.z, h.z, l.z); split2(v.w, h.w, l.w);
    H[i] = h; L[i] = l;
}

// ---------------- per-(b,t) column: softmax + K-th-largest radix select -> fp16 hi/lo ----------------
__global__ __launch_bounds__(256) void topk_softmax(const float* __restrict__ kvals,
                                                    ushrt* __restrict__ Wh, ushrt* __restrict__ Wl)
{
    const int b = blockIdx.x >> 9;
    const int t = blockIdx.x & 511;
    const size_t base = ((size_t)b * Tt + t) * Nn;
    const float* col = g_attn + base;
    const int tid = threadIdx.x;
    __shared__ float sh[8];
    __shared__ unsigned hist[256];
    __shared__ unsigned s_sel, s_rem;

    float x[4]; unsigned u[4];
    float mx = -3.4e38f;
#pragma unroll
    for (int i = 0; i < 4; i++) {
        x[i] = col[tid + 256 * i];
        mx = fmaxf(mx, x[i]);
        unsigned bits = __float_as_uint(x[i]);
        u[i] = (bits & 0x80000000u) ? ~bits : (bits | 0x80000000u);
    }
    for (int o = 16; o > 0; o >>= 1) mx = fmaxf(mx, __shfl_xor_sync(0xffffffffu, mx, o));
    if ((tid & 31) == 0) sh[tid >> 5] = mx;
    __syncthreads();
    if (tid == 0) { float m = sh[0]; for (int i = 1; i < 8; i++) m = fmaxf(m, sh[i]); sh[0] = m; }
    __syncthreads();
    mx = sh[0];
    __syncthreads();
    float s = 0.f;
#pragma unroll
    for (int i = 0; i < 4; i++) s += expf(x[i] - mx);
    for (int o = 16; o > 0; o >>= 1) s += __shfl_xor_sync(0xffffffffu, s, o);
    if ((tid & 31) == 0) sh[tid >> 5] = s;
    __syncthreads();
    if (tid == 0) { float m = 0.f; for (int i = 0; i < 8; i++) m += sh[i]; sh[0] = m; }
    __syncthreads();
    const float inv = 1.f / sh[0];

    int K = (int)rintf((float)Nn * kvals[b]);
    if (K < 0) K = 0;
    if (K > Nn) K = Nn;
    if (K == 0) {
#pragma unroll
        for (int i = 0; i < 4; i++) { Wh[base + tid + 256*i] = 0; Wl[base + tid + 256*i] = 0; }
        return;
    }
    unsigned thr = 0u;
    if (K < Nn) {
        unsigned pref = 0u, rem = (unsigned)K;
        for (int shift = 24; shift >= 0; shift -= 8) {
            hist[tid] = 0u;
            __syncthreads();
            unsigned hm = (shift == 24) ? 0u : (0xFFFFFFFFu << (shift + 8));
#pragma unroll
            for (int i = 0; i < 4; i++)
                if ((u[i] & hm) == pref) atomicAdd(&hist[(u[i] >> shift) & 255u], 1u);
            __syncthreads();
            for (int off = 1; off < 256; off <<= 1) {
                unsigned vv = (tid + off < 256) ? hist[tid + off] : 0u;
                __syncthreads();
                hist[tid] += vv;
                __syncthreads();
            }
            unsigned nxt = (tid < 255) ? hist[tid + 1] : 0u;
            if (hist[tid] >= rem && nxt < rem) { s_sel = (unsigned)tid; s_rem = rem - nxt; }
            __syncthreads();
            pref |= (s_sel << shift);
            rem = s_rem;
            __syncthreads();
        }
        thr = pref;
    }
#pragma unroll
    for (int i = 0; i < 4; i++) {
        float w = (u[i] >= thr) ? expf(x[i] - mx) * inv : 0.f;
        ushrt h, l;
        split2(w, h, l);
        Wh[base + tid + 256*i] = h;
        Wl[base + tid + 256*i] = l;
    }
}

// ---------------- BN stats ----------------
__global__ __launch_bounds__(256) void bn_partial(const float* __restrict__ X, float* __restrict__ part)
{
    const int tid = threadIdx.x;
    const float* base = X + (size_t)blockIdx.x * 128 * Cc;
    float s0=0,s1=0,s2=0,q0=0,q1=0,q2=0;
    for (int r = 0; r < 128; r++) {
        const float* row = base + (size_t)r * Cc;
        float a = row[tid], b = row[tid+256], c = row[tid+512];
        s0 += a; q0 = fmaf(a,a,q0);
        s1 += b; q1 = fmaf(b,b,q1);
        s2 += c; q2 = fmaf(c,c,q2);
    }
    float* p = part + (size_t)blockIdx.x * (2*Cc);
    p[tid]    = s0; p[tid+256]    = s1; p[tid+512]    = s2;
    p[Cc+tid] = q0; p[Cc+tid+256] = q1; p[Cc+tid+512] = q2;
}

__global__ void bn_finalize(const float* __restrict__ part, int nblk, float invN,
                            float* __restrict__ mu, float* __restrict__ rs)
{
    int c = blockIdx.x * 256 + threadIdx.x;
    if (c >= Cc) return;
    float s = 0.f, q = 0.f;
    for (int i = 0; i < nblk; i++) {
        s += part[(size_t)i * 2 * Cc + c];
        q += part[(size_t)i * 2 * Cc + Cc + c];
    }
    float m = s * invN;
    mu[c] = m;
    rs[c] = rsqrtf(q * invN - m * m + 1e-5f);
}

__global__ __launch_bounds__(256) void final_apply(float* __restrict__ out, const float* __restrict__ img,
                                                   const float* __restrict__ g, const float* __restrict__ bb)
{
    int i4 = blockIdx.x * 256 + threadIdx.x;
    float4 o = reinterpret_cast<float4*>(out)[i4];
    float4 im = reinterpret_cast<const float4*>(img)[i4];
    int c = (i4 * 4) % Cc;
    o.x = fmaxf(g[c+0]*(o.x - g_mu2[c+0])*g_rs2[c+0] + bb[c+0], 0.f) + im.x;
    o.y = fmaxf(g[c+1]*(o.y - g_mu2[c+1])*g_rs2[c+1] + bb[c+1], 0.f) + im.y;
    o.z = fmaxf(g[c+2]*(o.z - g_mu2[c+2])*g_rs2[c+2] + bb[c+2], 0.f) + im.z;
    o.w = fmaxf(g[c+3]*(o.w - g_mu2[c+3])*g_rs2[c+3] + bb[c+3], 0.f) + im.w;
    reinterpret_cast<float4*>(out)[i4] = o;
}

// ---------------- orchestration ----------------
extern "C" void kernel_launch(void* const* d_in, const int* in_sizes, int n_in,
                              void* d_out, int out_size)
{
    (void)in_sizes; (void)n_in; (void)out_size;
    const float* image = (const float*)d_in[0];
    const float* text  = (const float*)d_in[1];
    const float* kv    = (const float*)d_in[2];
    const float* Wc    = (const float*)d_in[3];
    const float* g1    = (const float*)d_in[5];
    const float* b1    = (const float*)d_in[6];
    const float* Wout  = (const float*)d_in[7];
    const float* bout  = (const float*)d_in[8];
    const float* g2    = (const float*)d_in[9];
    const float* b2    = (const float*)d_in[10];
    float* out = (float*)d_out;

    float *y1, *attn, *p1, *p2, *mu1, *rs1, *mu2, *rs2;
    ushrt *tx_h, *tx_l, *im_h, *im_l, *wcat_h, *wcat_l,
          *e1_h, *e1_l, *v_h, *v_l, *wt_h, *wt_l;
    cudaGetSymbolAddress((void**)&y1,   g_y1);
    cudaGetSymbolAddress((void**)&attn, g_attn);
    cudaGetSymbolAddress((void**)&p1,   g_p1);
    cudaGetSymbolAddress((void**)&p2,   g_p2);
    cudaGetSymbolAddress((void**)&mu1,  g_mu1);
    cudaGetSymbolAddress((void**)&rs1,  g_rs1);
    cudaGetSymbolAddress((void**)&mu2,  g_mu2);
    cudaGetSymbolAddress((void**)&rs2,  g_rs2);
    cudaGetSymbolAddress((void**)&tx_h, p_text_hi);  cudaGetSymbolAddress((void**)&tx_l, p_text_lo);
    cudaGetSymbolAddress((void**)&im_h, p_img_hi);   cudaGetSymbolAddress((void**)&im_l, p_img_lo);
    cudaGetSymbolAddress((void**)&wcat_h, p_Wcat_hi);cudaGetSymbolAddress((void**)&wcat_l, p_Wcat_lo);
    cudaGetSymbolAddress((void**)&e1_h, p_e1_hi);    cudaGetSymbolAddress((void**)&e1_l, p_e1_lo);
    cudaGetSymbolAddress((void**)&v_h,  p_v_hi);     cudaGetSymbolAddress((void**)&v_l,  p_v_lo);
    cudaGetSymbolAddress((void**)&wt_h, p_wt_hi);    cudaGetSymbolAddress((void**)&wt_l, p_wt_lo);

    cudaFuncSetAttribute(gemm_nt, cudaFuncAttributeMaxDynamicSharedMemorySize, NT_SMEM);
    cudaFuncSetAttribute(gemm_tn, cudaFuncAttributeMaxDynamicSharedMemorySize, TN_SMEM);

    const float inv_sqrtC = 0.03608439182435161f;  // 1/sqrt(768)

    // (0) pack text, (1) pack [Wc;Wout]
    pack_split<<<6144, 256>>>((const float4*)text, (ushort4*)tx_h, (ushort4*)tx_l, (long)ROWS1*Cc/4);
    pack_weights<<<1152, 256>>>((const float4*)Wc, (const float4*)Wout, (ushort4*)wcat_h, (ushort4*)wcat_l);

    // (2)+(3) merged G1G2, two halves: C[8192,1536] = text @ [Wc;Wout]^T
    //   cols 0..767 -> y1 (fp32), cols 768..1535 -> v (split fp16) + bout col bias
    for (int h = 0; h < 2; h++) {
        size_t ro = (size_t)h * 4096 * Cc;
        GP Pm = { tx_h + ro, tx_l + ro, wcat_h, wcat_l,
                  y1 + ro, v_h + ro, v_l + ro,
                  Cc, Cc, Cc, Cc, 0, 0, 0, bout, 1.f, Cc };
        gemm_nt<<<dim3(24, 32, 1), 128, NT_SMEM>>>(Pm);
    }

    // (4) pack image
    pack_split<<<12288, 256>>>((const float4*)image, (ushort4*)im_h, (ushort4*)im_l, (long)ROWS2*Cc/4);

    // BN1 stats + fused BN+relu+split-pack of e1
    bn_partial<<<64, 256>>>(y1, p1);
    bn_finalize<<<3, 256>>>(p1, 64, 1.f/(float)ROWS1, mu1, rs1);
    pack_bn_relu<<<6144, 256>>>((const float4*)y1, (ushort4*)e1_h, (ushort4*)e1_l, g1, b1);

    // G3: attn_t[b][512,1024] = (e1[b] @ image[b]^T) / sqrt(C)
    GP P3 = { e1_h, e1_l, im_h, im_l, attn, nullptr, nullptr,
              Cc, Nn, Cc, Cc, (long)Tt*Cc, (long)Nn*Cc, (long)Tt*Nn, nullptr, inv_sqrtC, 1<<30 };
    gemm_nt<<<dim3(16, 4, Bb), 128, NT_SMEM>>>(P3);

    // masked softmax weights -> fp16 hi/lo in [b][t][n]
    topk_softmax<<<Bb*Tt, 256>>>(kv, wt_h, wt_l);

    // G4 (TN): out[b][1024,768] = sum_t w[b][t][n] * v[b][t][c]
    GP P4 = { wt_h, wt_l, v_h, v_l, out, nullptr, nullptr,
              Tt, Cc, Nn, Cc, (long)Tt*Nn, (long)Tt*Cc, (long)Nn*Cc, nullptr, 1.f, 1<<30 };
    gemm_tn<<<dim3(12, 8, Bb), 128, TN_SMEM>>>(P4);

    // BN2 + final
    bn_partial<<<128, 256>>>(out, p2);
    bn_finalize<<<3, 256>>>(p2, 128, 1.f/(float)ROWS2, mu2, rs2);
    final_apply<<<12288, 256>>>(out, image, g2, b2);
}

// round 10
// speedup vs baseline: 1.0746x; 1.0350x over previous
#include <cuda_runtime.h>
#include <cuda_fp16.h>
#include <cstdint>
#include <math.h>

#define Bb 16
#define Nn 1024
#define Tt 512
#define Cc 768
#define ROWS1 (Bb*Tt)   // 8192
#define ROWS2 (Bb*Nn)   // 16384

typedef unsigned short ushrt;

// ---------------- device scratch ----------------
__device__ float g_y1[(size_t)ROWS1*Cc];        // text@Wc^T (pre-BN)
__device__ float g_attn[(size_t)Bb*Tt*Nn];      // attn_t[B,T,N] fp32
__device__ float g_p1[64*2*Cc];
__device__ float g_p2[128*2*Cc];
__device__ float g_mu1[Cc], g_rs1[Cc], g_mu2[Cc], g_rs2[Cc];

// packed fp16 hi/lo operands
__device__ ushrt p_text_hi[(size_t)ROWS1*Cc], p_text_lo[(size_t)ROWS1*Cc];
__device__ ushrt p_img_hi [(size_t)ROWS2*Cc], p_img_lo [(size_t)ROWS2*Cc];
__device__ ushrt p_Wcat_hi[2*Cc*Cc], p_Wcat_lo[2*Cc*Cc];                 // [Wc; Wout] rows
__device__ ushrt p_e1_hi[(size_t)ROWS1*Cc], p_e1_lo[(size_t)ROWS1*Cc];
__device__ ushrt p_v_hi[(size_t)ROWS1*Cc],  p_v_lo[(size_t)ROWS1*Cc];    // v[b][t][c]
__device__ ushrt p_wt_hi[(size_t)Bb*Tt*Nn], p_wt_lo[(size_t)Bb*Tt*Nn];   // w[b][t][n]

// ---------------- helpers ----------------
__device__ __forceinline__ uint32_t smem_u32(const void* p) {
    uint32_t a;
    asm("{ .reg .u64 t; cvta.to.shared.u64 t, %1; cvt.u32.u64 %0, t; }" : "=r"(a) : "l"(p));
    return a;
}
__device__ __forceinline__ void cpa16(uint32_t d, const void* s) {
    asm volatile("cp.async.cg.shared.global [%0], [%1], 16;" :: "r"(d), "l"(s));
}
__device__ __forceinline__ void cpa_commit() { asm volatile("cp.async.commit_group;" ::: "memory"); }
template<int N> __device__ __forceinline__ void cpa_wait() {
    asm volatile("cp.async.wait_group %0;" :: "n"(N) : "memory");
}
#define LDM4(r, addr) \
    asm volatile("ldmatrix.sync.aligned.m8n8.x4.shared.b16 {%0,%1,%2,%3}, [%4];" \
        : "=r"((r)[0]), "=r"((r)[1]), "=r"((r)[2]), "=r"((r)[3]) : "r"(addr))
#define LDM4T(r, addr) \
    asm volatile("ldmatrix.sync.aligned.m8n8.x4.trans.shared.b16 {%0,%1,%2,%3}, [%4];" \
        : "=r"((r)[0]), "=r"((r)[1]), "=r"((r)[2]), "=r"((r)[3]) : "r"(addr))
#define MMA16816(d, a, b0, b1) \
    asm volatile("mma.sync.aligned.m16n8k16.row.col.f32.f16.f16.f32 " \
        "{%0,%1,%2,%3}, {%4,%5,%6,%7}, {%8,%9}, {%0,%1,%2,%3};" \
        : "+f"((d)[0]), "+f"((d)[1]), "+f"((d)[2]), "+f"((d)[3]) \
        : "r"((a)[0]), "r"((a)[1]), "r"((a)[2]), "r"((a)[3]), "r"(b0), "r"(b1))

__device__ __forceinline__ void split2(float x, ushrt& h, ushrt& l) {
    __half hh = __float2half_rn(x);
    float fh = __half2float(hh);
    __half ll = __float2half_rn(x - fh);
    h = *reinterpret_cast<ushrt*>(&hh);
    l = *reinterpret_cast<ushrt*>(&ll);
}

struct GP {
    const ushrt *Ah, *Al, *Bh, *Bl;
    float* C; ushrt *Ch, *Cl;          // fp32 out, or split-fp16 out region (vmode)
    int K, Nc, ldA, ldB;
    long sA, sB, sC;
    const float* bias;                 // column bias, vmode only
    float alpha;
    int nsplit;                        // n0 >= nsplit -> vmode split output
};

// ---------------- fp16x3 MMA GEMM body ----------------
// CTA tile 128(M) x 64(N), BK=32, 128 threads (4 warps 2x2), warp tile 64x32.
// TN=false: A row-major [M][ldA], B row-major [N][ldB].
// TN=true:  A K-major [K][ldA], B K-major [K][ldB] (both trans-loaded).
// 2-stage cp.async double buffer -> 3 CTAs/SM (12 warps) for latency hiding.
template<bool TN>
__device__ __forceinline__ void gemm_body(const GP& P, int bx, int by, int bz, char* smem)
{
    constexpr int A_TILE = TN ? 8704 : 10240;   // TN: [32][136]; NT: [128][40]
    constexpr int B_TILE = TN ? 4608 : 5120;    // TN: [32][72];  NT: [64][40]
    constexpr int STAGE  = 2*A_TILE + 2*B_TILE;
    const int tid = threadIdx.x, wid = tid >> 5, lid = tid & 31;
    const int m0 = by * 128, n0 = bx * 64;
    const int K = P.K, nk = K >> 5, ldA = P.ldA, ldB = P.ldB;
    const uint32_t sb = smem_u32(smem);

    const ushrt *gAh, *gAl, *gBh, *gBl;
    if constexpr (TN) {
        gAh = P.Ah + (size_t)bz * P.sA + m0;
        gAl = P.Al + (size_t)bz * P.sA + m0;
        gBh = P.Bh + (size_t)bz * P.sB + n0;
        gBl = P.Bl + (size_t)bz * P.sB + n0;
    } else {
        gAh = P.Ah + (size_t)bz * P.sA + (size_t)m0 * ldA;
        gAl = P.Al + (size_t)bz * P.sA + (size_t)m0 * ldA;
        gBh = P.Bh + (size_t)bz * P.sB + (size_t)n0 * ldB;
        gBl = P.Bl + (size_t)bz * P.sB + (size_t)n0 * ldB;
    }

    uint32_t a_sm[4]; size_t a_g[4];
    uint32_t b_sm[2]; size_t b_g[2];
#pragma unroll
    for (int j = 0; j < 4; j++) {
        int i = tid + 128 * j;
        if constexpr (TN) { int r = i >> 4, c8 = (i & 15) * 8; a_sm[j] = (uint32_t)(r * 272 + c8 * 2); a_g[j] = (size_t)r * ldA + c8; }
        else              { int r = i >> 2, c8 = (i & 3) * 8;  a_sm[j] = (uint32_t)(r * 80 + c8 * 2);  a_g[j] = (size_t)r * ldA + c8; }
    }
#pragma unroll
    for (int j = 0; j < 2; j++) {
        int i = tid + 128 * j;
        if constexpr (TN) { int r = i >> 3, c8 = (i & 7) * 8; b_sm[j] = (uint32_t)(r * 144 + c8 * 2); b_g[j] = (size_t)r * ldB + c8; }
        else              { int r = i >> 2, c8 = (i & 3) * 8; b_sm[j] = (uint32_t)(r * 80 + c8 * 2);  b_g[j] = (size_t)r * ldB + c8; }
    }

    auto load_chunk = [&](int c, int s) {
        uint32_t ds = sb + (uint32_t)s * STAGE;
        size_t aoff = TN ? (size_t)c * 32 * ldA : (size_t)c * 32;
        size_t boff = TN ? (size_t)c * 32 * ldB : (size_t)c * 32;
#pragma unroll
        for (int j = 0; j < 4; j++) {
            cpa16(ds + a_sm[j],          gAh + aoff + a_g[j]);
            cpa16(ds + A_TILE + a_sm[j], gAl + aoff + a_g[j]);
        }
#pragma unroll
        for (int j = 0; j < 2; j++) {
            cpa16(ds + 2*A_TILE + b_sm[j],          gBh + boff + b_g[j]);
            cpa16(ds + 2*A_TILE + B_TILE + b_sm[j], gBl + boff + b_g[j]);
        }
    };

    const int wm0 = (wid >> 1) * 64, wn0 = (wid & 1) * 32;
    uint32_t a_fb, b_fb;
    if constexpr (TN) {
        int k_off = (lid & 7) + ((lid >> 4) << 3);
        int x_off = ((lid >> 3) & 1) << 3;
        a_fb = (uint32_t)(k_off * 272 + (wm0 + x_off) * 2);
        b_fb = (uint32_t)(2*A_TILE + k_off * 144 + (wn0 + x_off) * 2);
    } else {
        a_fb = (uint32_t)(((wm0 + (lid & 15)) * 40 + (lid >> 4) * 8) * 2);
        b_fb = (uint32_t)(2*A_TILE + ((wn0 + (lid & 15)) * 40 + (lid >> 4) * 8) * 2);
    }

    float acc[4][4][4] = {};

    load_chunk(0, 0);
    cpa_commit();

    for (int c = 0; c < nk; c++) {
        if (c + 1 < nk) {
            load_chunk(c + 1, (c + 1) & 1);
            cpa_commit();
            cpa_wait<1>();
        } else {
            cpa_wait<0>();
        }
        __syncthreads();

        const uint32_t st = sb + (uint32_t)(c & 1) * STAGE;
#pragma unroll
        for (int kk = 0; kk < 2; kk++) {
            uint32_t Ahf[4][4], Alf[4][4], Bhf[2][4], Blf[2][4];
            if constexpr (TN) {
                const uint32_t ak = st + a_fb + kk * 4352;     // 16 k-rows * 272B
                const uint32_t bk = st + b_fb + kk * 2304;     // 16 k-rows * 144B
#pragma unroll
                for (int mi = 0; mi < 4; mi++) {
                    LDM4T(Ahf[mi], ak + mi * 32);
                    LDM4T(Alf[mi], ak + A_TILE + mi * 32);
                }
#pragma unroll
                for (int p = 0; p < 2; p++) {
                    LDM4T(Bhf[p], bk + p * 32);
                    LDM4T(Blf[p], bk + B_TILE + p * 32);
                }
            } else {
                const uint32_t ak = st + a_fb + kk * 32;
                const uint32_t bk = st + b_fb + kk * 32;
#pragma unroll
                for (int mi = 0; mi < 4; mi++) {
                    LDM4(Ahf[mi], ak + mi * 1280);
                    LDM4(Alf[mi], ak + A_TILE + mi * 1280);
                }
#pragma unroll
                for (int p = 0; p < 2; p++) {
                    LDM4(Bhf[p], bk + p * 1280);
                    LDM4(Blf[p], bk + B_TILE + p * 1280);
                }
            }
            // products outermost: 16-MMA spacing between same-acc RAW
#pragma unroll
            for (int mi = 0; mi < 4; mi++)
#pragma unroll
                for (int nj = 0; nj < 4; nj++)
                    MMA16816(acc[mi][nj], Ahf[mi], Bhf[nj>>1][nj&1], Bhf[nj>>1][(nj&1)+2]);
#pragma unroll
            for (int mi = 0; mi < 4; mi++)
#pragma unroll
                for (int nj = 0; nj < 4; nj++)
                    MMA16816(acc[mi][nj], Ahf[mi], Blf[nj>>1][nj&1], Blf[nj>>1][(nj&1)+2]);
#pragma unroll
            for (int mi = 0; mi < 4; mi++)
#pragma unroll
                for (int nj = 0; nj < 4; nj++)
                    MMA16816(acc[mi][nj], Alf[mi], Bhf[nj>>1][nj&1], Bhf[nj>>1][(nj&1)+2]);
        }
        __syncthreads();   // protect buffer (c&1) before iter c+1 overwrites ((c+2)&1 == c&1)... (c+1 writes (c+1)&1; c+2 writes c&1)
    }

    // epilogue
    const int qr = lid >> 2, qc = (lid & 3) * 2;
    const bool vmode = (n0 >= P.nsplit);
#pragma unroll
    for (int mi = 0; mi < 4; mi++) {
        const int row0 = m0 + wm0 + mi * 16 + qr;
        const int row1 = row0 + 8;
#pragma unroll
        for (int nj = 0; nj < 4; nj++) {
            const int col = n0 + wn0 + nj * 8 + qc;
            float v00 = acc[mi][nj][0] * P.alpha;
            float v01 = acc[mi][nj][1] * P.alpha;
            float v10 = acc[mi][nj][2] * P.alpha;
            float v11 = acc[mi][nj][3] * P.alpha;
            if (vmode) {
                const int c0 = col - P.nsplit;
                if (P.bias) {
                    float b0 = P.bias[c0], b1 = P.bias[c0 + 1];
                    v00 += b0; v01 += b1; v10 += b0; v11 += b1;
                }
                ushort2 h0, l0, h1, l1;
                split2(v00, h0.x, l0.x); split2(v01, h0.y, l0.y);
                split2(v10, h1.x, l1.x); split2(v11, h1.y, l1.y);
                size_t o0 = (size_t)row0 * P.Nc + c0;
                size_t o1 = (size_t)row1 * P.Nc + c0;
                *reinterpret_cast<ushort2*>(P.Ch + o0) = h0;
                *reinterpret_cast<ushort2*>(P.Cl + o0) = l0;
                *reinterpret_cast<ushort2*>(P.Ch + o1) = h1;
                *reinterpret_cast<ushort2*>(P.Cl + o1) = l1;
            } else {
                float* Cb = P.C + (size_t)bz * P.sC;
                float2 a0, a1;
                a0.x = v00; a0.y = v01; a1.x = v10; a1.y = v11;
                *reinterpret_cast<float2*>(Cb + (size_t)row0 * P.Nc + col) = a0;
                *reinterpret_cast<float2*>(Cb + (size_t)row1 * P.Nc + col) = a1;
            }
        }
    }
}

#define NT_SMEM (2*(2*10240 + 2*5120))   // 61440 -> 3 CTAs/SM
#define TN_SMEM (2*(2*8704  + 2*4608))   // 53248 -> 3 CTAs/SM

__global__ void __launch_bounds__(128, 3) gemm_nt(GP P) {
    extern __shared__ __align__(16) char smem[];
    gemm_body<false>(P, blockIdx.x, blockIdx.y, blockIdx.z, smem);
}
__global__ void __launch_bounds__(128, 3) gemm_tn(GP P) {
    extern __shared__ __align__(16) char smem[];
    gemm_body<true>(P, blockIdx.x, blockIdx.y, blockIdx.z, smem);
}

// ---------------- pack kernels ----------------
__global__ __launch_bounds__(256) void pack_weights(const float4* __restrict__ Wc,
                                                    const float4* __restrict__ Wo,
                                                    ushort4* __restrict__ H, ushort4* __restrict__ L)
{
    const long half = (long)Cc * Cc / 4;
    long i = (long)blockIdx.x * 256 + threadIdx.x;
    if (i >= 2 * half) return;
    float4 v = (i < half) ? Wc[i] : Wo[i - half];
    ushort4 h, l;
    split2(v.x, h.x, l.x); split2(v.y, h.y, l.y);
    split2(v.z, h.z, l.z); split2(v.w, h.w, l.w);
    H[i] = h; L[i] = l;
}

__global__ __launch_bounds__(256) void pack_split(const float4* __restrict__ X,
                                                  ushort4* __restrict__ H, ushort4* __restrict__ L, long n4)
{
    long i = (long)blockIdx.x * 256 + threadIdx.x;
    if (i >= n4) return;
    float4 v = X[i];
    ushort4 h, l;
    split2(v.x, h.x, l.x); split2(v.y, h.y, l.y);
    split2(v.z, h.z, l.z); split2(v.w, h.w, l.w);
    H[i] = h; L[i] = l;
}

__global__ __launch_bounds__(256) void pack_bn_relu(const float4* __restrict__ X,
                                                    ushort4* __restrict__ H, ushort4* __restrict__ L,
                                                    const float* __restrict__ g, const float* __restrict__ bb)
{
    long i = (long)blockIdx.x * 256 + threadIdx.x;   // over ROWS1*Cc/4
    float4 v = X[i];
    int ch = (int)((i * 4) % Cc);
    v.x = fmaxf(g[ch+0]*(v.x - g_mu1[ch+0])*g_rs1[ch+0] + bb[ch+0], 0.f);
    v.y = fmaxf(g[ch+1]*(v.y - g_mu1[ch+1])*g_rs1[ch+1] + bb[ch+1], 0.f);
    v.z = fmaxf(g[ch+2]*(v.z - g_mu1[ch+2])*g_rs1[ch+2] + bb[ch+2], 0.f);
    v.w = fmaxf(g[ch+3]*(v.w - g_mu1[ch+3])*g_rs1[ch+3] + bb[ch+3], 0.f);
    ushort4 h, l;
    split2(v.x, h.x, l.x); split2(v.y, h.y, l.y);
    split2(v.z, h.z, l.z); split2(v.w, h.w, l.w);
    H[i] = h; L[i] = l;
}

// ---------------- per-(b,t) column: softmax + K-th-largest radix select -> fp16 hi/lo ----------------
__global__ __launch_bounds__(256) void topk_softmax(const float* __restrict__ kvals,
                                                    ushrt* __restrict__ Wh, ushrt* __restrict__ Wl)
{
    const int b = blockIdx.x >> 9;
    const int t = blockIdx.x & 511;
    const size_t base = ((size_t)b * Tt + t) * Nn;
    const float* col = g_attn + base;
    const int tid = threadIdx.x;
    __shared__ float sh[8];
    __shared__ unsigned hist[256];
    __shared__ unsigned s_sel, s_rem;

    float x[4]; unsigned u[4];
    float mx = -3.4e38f;
#pragma unroll
    for (int i = 0; i < 4; i++) {
        x[i] = col[tid + 256 * i];
        mx = fmaxf(mx, x[i]);
        unsigned bits = __float_as_uint(x[i]);
        u[i] = (bits & 0x80000000u) ? ~bits : (bits | 0x80000000u);
    }
    for (int o = 16; o > 0; o >>= 1) mx = fmaxf(mx, __shfl_xor_sync(0xffffffffu, mx, o));
    if ((tid & 31) == 0) sh[tid >> 5] = mx;
    __syncthreads();
    if (tid == 0) { float m = sh[0]; for (int i = 1; i < 8; i++) m = fmaxf(m, sh[i]); sh[0] = m; }
    __syncthreads();
    mx = sh[0];
    __syncthreads();
    float s = 0.f;
#pragma unroll
    for (int i = 0; i < 4; i++) s += expf(x[i] - mx);
    for (int o = 16; o > 0; o >>= 1) s += __shfl_xor_sync(0xffffffffu, s, o);
    if ((tid & 31) == 0) sh[tid >> 5] = s;
    __syncthreads();
    if (tid == 0) { float m = 0.f; for (int i = 0; i < 8; i++) m += sh[i]; sh[0] = m; }
    __syncthreads();
    const float inv = 1.f / sh[0];

    int K = (int)rintf((float)Nn * kvals[b]);
    if (K < 0) K = 0;
    if (K > Nn) K = Nn;
    if (K == 0) {
#pragma unroll
        for (int i = 0; i < 4; i++) { Wh[base + tid + 256*i] = 0; Wl[base + tid + 256*i] = 0; }
        return;
    }
    unsigned thr = 0u;
    if (K < Nn) {
        unsigned pref = 0u, rem = (unsigned)K;
        for (int shift = 24; shift >= 0; shift -= 8) {
            hist[tid] = 0u;
            __syncthreads();
            unsigned hm = (shift == 24) ? 0u : (0xFFFFFFFFu << (shift + 8));
#pragma unroll
            for (int i = 0; i < 4; i++)
                if ((u[i] & hm) == pref) atomicAdd(&hist[(u[i] >> shift) & 255u], 1u);
            __syncthreads();
            for (int off = 1; off < 256; off <<= 1) {
                unsigned vv = (tid + off < 256) ? hist[tid + off] : 0u;
                __syncthreads();
                hist[tid] += vv;
                __syncthreads();
            }
            unsigned nxt = (tid < 255) ? hist[tid + 1] : 0u;
            if (hist[tid] >= rem && nxt < rem) { s_sel = (unsigned)tid; s_rem = rem - nxt; }
            __syncthreads();
            pref |= (s_sel << shift);
            rem = s_rem;
            __syncthreads();
        }
        thr = pref;
    }
#pragma unroll
    for (int i = 0; i < 4; i++) {
        float w = (u[i] >= thr) ? expf(x[i] - mx) * inv : 0.f;
        ushrt h, l;
        split2(w, h, l);
        Wh[base + tid + 256*i] = h;
        Wl[base + tid + 256*i] = l;
    }
}

// ---------------- BN stats ----------------
__global__ __launch_bounds__(256) void bn_partial(const float* __restrict__ X, float* __restrict__ part)
{
    const int tid = threadIdx.x;
    const float* base = X + (size_t)blockIdx.x * 128 * Cc;
    float s0=0,s1=0,s2=0,q0=0,q1=0,q2=0;
    for (int r = 0; r < 128; r++) {
        const float* row = base + (size_t)r * Cc;
        float a = row[tid], b = row[tid+256], c = row[tid+512];
        s0 += a; q0 = fmaf(a,a,q0);
        s1 += b; q1 = fmaf(b,b,q1);
        s2 += c; q2 = fmaf(c,c,q2);
    }
    float* p = part + (size_t)blockIdx.x * (2*Cc);
    p[tid]    = s0; p[tid+256]    = s1; p[tid+512]    = s2;
    p[Cc+tid] = q0; p[Cc+tid+256] = q1; p[Cc+tid+512] = q2;
}

__global__ void bn_finalize(const float* __restrict__ part, int nblk, float invN,
                            float* __restrict__ mu, float* __restrict__ rs)
{
    int c = blockIdx.x * 256 + threadIdx.x;
    if (c >= Cc) return;
    float s = 0.f, q = 0.f;
    for (int i = 0; i < nblk; i++) {
        s += part[(size_t)i * 2 * Cc + c];
        q += part[(size_t)i * 2 * Cc + Cc + c];
    }
    float m = s * invN;
    mu[c] = m;
    rs[c] = rsqrtf(q * invN - m * m + 1e-5f);
}

__global__ __launch_bounds__(256) void final_apply(float* __restrict__ out, const float* __restrict__ img,
                                                   const float* __restrict__ g, const float* __restrict__ bb)
{
    int i4 = blockIdx.x * 256 + threadIdx.x;
    float4 o = reinterpret_cast<float4*>(out)[i4];
    float4 im = reinterpret_cast<const float4*>(img)[i4];
    int c = (i4 * 4) % Cc;
    o.x = fmaxf(g[c+0]*(o.x - g_mu2[c+0])*g_rs2[c+0] + bb[c+0], 0.f) + im.x;
    o.y = fmaxf(g[c+1]*(o.y - g_mu2[c+1])*g_rs2[c+1] + bb[c+1], 0.f) + im.y;
    o.z = fmaxf(g[c+2]*(o.z - g_mu2[c+2])*g_rs2[c+2] + bb[c+2], 0.f) + im.z;
    o.w = fmaxf(g[c+3]*(o.w - g_mu2[c+3])*g_rs2[c+3] + bb[c+3], 0.f) + im.w;
    reinterpret_cast<float4*>(out)[i4] = o;
}

// ---------------- orchestration ----------------
extern "C" void kernel_launch(void* const* d_in, const int* in_sizes, int n_in,
                              void* d_out, int out_size)
{
    (void)in_sizes; (void)n_in; (void)out_size;
    const float* image = (const float*)d_in[0];
    const float* text  = (const float*)d_in[1];
    const float* kv    = (const float*)d_in[2];
    const float* Wc    = (const float*)d_in[3];
    const float* g1    = (const float*)d_in[5];
    const float* b1    = (const float*)d_in[6];
    const float* Wout  = (const float*)d_in[7];
    const float* bout  = (const float*)d_in[8];
    const float* g2    = (const float*)d_in[9];
    const float* b2    = (const float*)d_in[10];
    float* out = (float*)d_out;

    float *y1, *attn, *p1, *p2, *mu1, *rs1, *mu2, *rs2;
    ushrt *tx_h, *tx_l, *im_h, *im_l, *wcat_h, *wcat_l,
          *e1_h, *e1_l, *v_h, *v_l, *wt_h, *wt_l;
    cudaGetSymbolAddress((void**)&y1,   g_y1);
    cudaGetSymbolAddress((void**)&attn, g_attn);
    cudaGetSymbolAddress((void**)&p1,   g_p1);
    cudaGetSymbolAddress((void**)&p2,   g_p2);
    cudaGetSymbolAddress((void**)&mu1,  g_mu1);
    cudaGetSymbolAddress((void**)&rs1,  g_rs1);
    cudaGetSymbolAddress((void**)&mu2,  g_mu2);
    cudaGetSymbolAddress((void**)&rs2,  g_rs2);
    cudaGetSymbolAddress((void**)&tx_h, p_text_hi);  cudaGetSymbolAddress((void**)&tx_l, p_text_lo);
    cudaGetSymbolAddress((void**)&im_h, p_img_hi);   cudaGetSymbolAddress((void**)&im_l, p_img_lo);
    cudaGetSymbolAddress((void**)&wcat_h, p_Wcat_hi);cudaGetSymbolAddress((void**)&wcat_l, p_Wcat_lo);
    cudaGetSymbolAddress((void**)&e1_h, p_e1_hi);    cudaGetSymbolAddress((void**)&e1_l, p_e1_lo);
    cudaGetSymbolAddress((void**)&v_h,  p_v_hi);     cudaGetSymbolAddress((void**)&v_l,  p_v_lo);
    cudaGetSymbolAddress((void**)&wt_h, p_wt_hi);    cudaGetSymbolAddress((void**)&wt_l, p_wt_lo);

    cudaFuncSetAttribute(gemm_nt, cudaFuncAttributeMaxDynamicSharedMemorySize, NT_SMEM);
    cudaFuncSetAttribute(gemm_tn, cudaFuncAttributeMaxDynamicSharedMemorySize, TN_SMEM);

    const float inv_sqrtC = 0.03608439182435161f;  // 1/sqrt(768)

    // (0) pack text, (1) pack [Wc;Wout]
    pack_split<<<6144, 256>>>((const float4*)text, (ushort4*)tx_h, (ushort4*)tx_l, (long)ROWS1*Cc/4);
    pack_weights<<<1152, 256>>>((const float4*)Wc, (const float4*)Wout, (ushort4*)wcat_h, (ushort4*)wcat_l);

    // (2)+(3) merged G1G2, two halves: C[8192,1536] = text @ [Wc;Wout]^T
    //   cols 0..767 -> y1 (fp32), cols 768..1535 -> v (split fp16) + bout col bias
    for (int h = 0; h < 2; h++) {
        size_t ro = (size_t)h * 4096 * Cc;
        GP Pm = { tx_h + ro, tx_l + ro, wcat_h, wcat_l,
                  y1 + ro, v_h + ro, v_l + ro,
                  Cc, Cc, Cc, Cc, 0, 0, 0, bout, 1.f, Cc };
        gemm_nt<<<dim3(24, 32, 1), 128, NT_SMEM>>>(Pm);
    }

    // (4) pack image
    pack_split<<<12288, 256>>>((const float4*)image, (ushort4*)im_h, (ushort4*)im_l, (long)ROWS2*Cc/4);

    // BN1 stats + fused BN+relu+split-pack of e1
    bn_partial<<<64, 256>>>(y1, p1);
    bn_finalize<<<3, 256>>>(p1, 64, 1.f/(float)ROWS1, mu1, rs1);
    pack_bn_relu<<<6144, 256>>>((const float4*)y1, (ushort4*)e1_h, (ushort4*)e1_l, g1, b1);

    // G3: attn_t[b][512,1024] = (e1[b] @ image[b]^T) / sqrt(C)
    GP P3 = { e1_h, e1_l, im_h, im_l, attn, nullptr, nullptr,
              Cc, Nn, Cc, Cc, (long)Tt*Cc, (long)Nn*Cc, (long)Tt*Nn, nullptr, inv_sqrtC, 1<<30 };
    gemm_nt<<<dim3(16, 4, Bb), 128, NT_SMEM>>>(P3);

    // masked softmax weights -> fp16 hi/lo in [b][t][n]
    topk_softmax<<<Bb*Tt, 256>>>(kv, wt_h, wt_l);

    // G4 (TN): out[b][1024,768] = sum_t w[b][t][n] * v[b][t][c]
    GP P4 = { wt_h, wt_l, v_h, v_l, out, nullptr, nullptr,
              Tt, Cc, Nn, Cc, (long)Tt*Nn, (long)Tt*Cc, (long)Nn*Cc, nullptr, 1.f, 1<<30 };
    gemm_tn<<<dim3(12, 8, Bb), 128, TN_SMEM>>>(P4);

    // BN2 + final
    bn_partial<<<128, 256>>>(out, p2);
    bn_finalize<<<3, 256>>>(p2, 128, 1.f/(float)ROWS2, mu2, rs2);
    final_apply<<<12288, 256>>>(out, image, g2, b2);
}

// round 13
// speedup vs baseline: 1.0897x; 1.0140x over previous
#include <cuda_runtime.h>
#include <cuda_fp16.h>
#include <cstdint>
#include <math.h>

#define Bb 16
#define Nn 1024
#define Tt 512
#define Cc 768
#define ROWS1 (Bb*Tt)   // 8192
#define ROWS2 (Bb*Nn)   // 16384

typedef unsigned short ushrt;

// ---------------- device scratch ----------------
__device__ float g_y1[(size_t)ROWS1*Cc];        // text@Wc^T (pre-BN)
__device__ float g_attn[(size_t)Bb*Tt*Nn];      // attn_t[B,T,N] fp32
__device__ float g_p1[64*2*Cc];
__device__ float g_p2[128*2*Cc];
__device__ float g_mu1[Cc], g_rs1[Cc], g_mu2[Cc], g_rs2[Cc];

// packed fp16 hi/lo operands
__device__ ushrt p_text_hi[(size_t)ROWS1*Cc], p_text_lo[(size_t)ROWS1*Cc];
__device__ ushrt p_img_hi [(size_t)ROWS2*Cc], p_img_lo [(size_t)ROWS2*Cc];
__device__ ushrt p_Wcat_hi[2*Cc*Cc], p_Wcat_lo[2*Cc*Cc];                 // [Wc; Wout] rows
__device__ ushrt p_e1_hi[(size_t)ROWS1*Cc], p_e1_lo[(size_t)ROWS1*Cc];
__device__ ushrt p_v_hi[(size_t)ROWS1*Cc],  p_v_lo[(size_t)ROWS1*Cc];    // v[b][t][c]
__device__ ushrt p_wt_hi[(size_t)Bb*Tt*Nn], p_wt_lo[(size_t)Bb*Tt*Nn];   // w[b][t][n]

// ---------------- helpers ----------------
__device__ __forceinline__ uint32_t smem_u32(const void* p) {
    uint32_t a;
    asm("{ .reg .u64 t; cvta.to.shared.u64 t, %1; cvt.u32.u64 %0, t; }" : "=r"(a) : "l"(p));
    return a;
}
__device__ __forceinline__ void cpa16(uint32_t d, const void* s) {
    asm volatile("cp.async.cg.shared.global [%0], [%1], 16;" :: "r"(d), "l"(s));
}
__device__ __forceinline__ void cpa_commit() { asm volatile("cp.async.commit_group;" ::: "memory"); }
template<int N> __device__ __forceinline__ void cpa_wait() {
    asm volatile("cp.async.wait_group %0;" :: "n"(N) : "memory");
}
#define LDM4(r, addr) \
    asm volatile("ldmatrix.sync.aligned.m8n8.x4.shared.b16 {%0,%1,%2,%3}, [%4];" \
        : "=r"((r)[0]), "=r"((r)[1]), "=r"((r)[2]), "=r"((r)[3]) : "r"(addr))
#define LDM4T(r, addr) \
    asm volatile("ldmatrix.sync.aligned.m8n8.x4.trans.shared.b16 {%0,%1,%2,%3}, [%4];" \
        : "=r"((r)[0]), "=r"((r)[1]), "=r"((r)[2]), "=r"((r)[3]) : "r"(addr))
#define MMA16816(d, a, b0, b1) \
    asm volatile("mma.sync.aligned.m16n8k16.row.col.f32.f16.f16.f32 " \
        "{%0,%1,%2,%3}, {%4,%5,%6,%7}, {%8,%9}, {%0,%1,%2,%3};" \
        : "+f"((d)[0]), "+f"((d)[1]), "+f"((d)[2]), "+f"((d)[3]) \
        : "r"((a)[0]), "r"((a)[1]), "r"((a)[2]), "r"((a)[3]), "r"(b0), "r"(b1))

__device__ __forceinline__ void split2(float x, ushrt& h, ushrt& l) {
    __half hh = __float2half_rn(x);
    float fh = __half2float(hh);
    __half ll = __float2half_rn(x - fh);
    h = *reinterpret_cast<ushrt*>(&hh);
    l = *reinterpret_cast<ushrt*>(&ll);
}

struct GP {
    const ushrt *Ah, *Al, *Bh, *Bl;
    float* C; ushrt *Ch, *Cl;          // fp32 out, or split-fp16 out region (vmode)
    int K, Nc, ldA, ldB;
    long sA, sB, sC;
    const float* bias;                 // column bias, vmode only
    float alpha;
    int nsplit;                        // n0 >= nsplit -> vmode split output
};

// ---------------- fp16x3 MMA GEMM body ----------------
// CTA tile 128(M) x 64(N), BK=32, 128 threads (4 warps 2x2), warp tile 64x32.
// TN=false: A row-major [M][ldA], B row-major [N][ldB].
// TN=true:  A K-major [K][ldA], B K-major [K][ldB] (both trans-loaded).
// 3-stage cp.async pipeline, ONE barrier per chunk, fragment software pipeline:
// both kk-halves' hi-fragments hoisted so LDSM of kk=1 overlaps MMAs of kk=0.
template<bool TN>
__device__ __forceinline__ void gemm_body(const GP& P, int bx, int by, int bz, char* smem)
{
    constexpr int A_TILE = TN ? 8704 : 10240;   // TN: [32][136]; NT: [128][40]
    constexpr int B_TILE = TN ? 4608 : 5120;    // TN: [32][72];  NT: [64][40]
    constexpr int STAGE  = 2*A_TILE + 2*B_TILE;
    const int tid = threadIdx.x, wid = tid >> 5, lid = tid & 31;
    const int m0 = by * 128, n0 = bx * 64;
    const int K = P.K, nk = K >> 5, ldA = P.ldA, ldB = P.ldB;
    const uint32_t sb = smem_u32(smem);

    const ushrt *gAh, *gAl, *gBh, *gBl;
    if constexpr (TN) {
        gAh = P.Ah + (size_t)bz * P.sA + m0;
        gAl = P.Al + (size_t)bz * P.sA + m0;
        gBh = P.Bh + (size_t)bz * P.sB + n0;
        gBl = P.Bl + (size_t)bz * P.sB + n0;
    } else {
        gAh = P.Ah + (size_t)bz * P.sA + (size_t)m0 * ldA;
        gAl = P.Al + (size_t)bz * P.sA + (size_t)m0 * ldA;
        gBh = P.Bh + (size_t)bz * P.sB + (size_t)n0 * ldB;
        gBl = P.Bl + (size_t)bz * P.sB + (size_t)n0 * ldB;
    }

    uint32_t a_sm[4]; int a_g[4];
    uint32_t b_sm[2]; int b_g[2];
#pragma unroll
    for (int j = 0; j < 4; j++) {
        int i = tid + 128 * j;
        if constexpr (TN) { int r = i >> 4, c8 = (i & 15) * 8; a_sm[j] = (uint32_t)(r * 272 + c8 * 2); a_g[j] = r * ldA + c8; }
        else              { int r = i >> 2, c8 = (i & 3) * 8;  a_sm[j] = (uint32_t)(r * 80 + c8 * 2);  a_g[j] = r * ldA + c8; }
    }
#pragma unroll
    for (int j = 0; j < 2; j++) {
        int i = tid + 128 * j;
        if constexpr (TN) { int r = i >> 3, c8 = (i & 7) * 8; b_sm[j] = (uint32_t)(r * 144 + c8 * 2); b_g[j] = r * ldB + c8; }
        else              { int r = i >> 2, c8 = (i & 3) * 8; b_sm[j] = (uint32_t)(r * 80 + c8 * 2);  b_g[j] = r * ldB + c8; }
    }

    auto load_chunk = [&](int c, int s) {
        uint32_t ds = sb + (uint32_t)s * STAGE;
        size_t aoff = TN ? (size_t)c * 32 * ldA : (size_t)c * 32;
        size_t boff = TN ? (size_t)c * 32 * ldB : (size_t)c * 32;
#pragma unroll
        for (int j = 0; j < 4; j++) {
            cpa16(ds + a_sm[j],          gAh + aoff + a_g[j]);
            cpa16(ds + A_TILE + a_sm[j], gAl + aoff + a_g[j]);
        }
#pragma unroll
        for (int j = 0; j < 2; j++) {
            cpa16(ds + 2*A_TILE + b_sm[j],          gBh + boff + b_g[j]);
            cpa16(ds + 2*A_TILE + B_TILE + b_sm[j], gBl + boff + b_g[j]);
        }
    };

    const int wm0 = (wid >> 1) * 64, wn0 = (wid & 1) * 32;
    uint32_t a_fb, b_fb;
    if constexpr (TN) {
        int k_off = (lid & 7) + ((lid >> 4) << 3);
        int x_off = ((lid >> 3) & 1) << 3;
        a_fb = (uint32_t)(k_off * 272 + (wm0 + x_off) * 2);
        b_fb = (uint32_t)(2*A_TILE + k_off * 144 + (wn0 + x_off) * 2);
    } else {
        a_fb = (uint32_t)(((wm0 + (lid & 15)) * 40 + (lid >> 4) * 8) * 2);
        b_fb = (uint32_t)(2*A_TILE + ((wn0 + (lid & 15)) * 40 + (lid >> 4) * 8) * 2);
    }

    float acc[4][4][4] = {};

    load_chunk(0, 0);
    cpa_commit();
    load_chunk(1, 1);
    cpa_commit();

    for (int c = 0; c < nk; c++) {
        cpa_wait<1>();
        __syncthreads();                       // all warps done reading stage (c-1)%3
        if (c + 2 < nk) load_chunk(c + 2, (c + 2) % 3);   // writes (c+2)%3 == (c-1)%3: safe
        cpa_commit();

        const uint32_t st = sb + (uint32_t)(c % 3) * STAGE;
        uint32_t Ahf[2][4][4], Bhf[2][2][4], Blf[2][2][4], Alf[4][4];

        // hoisted loads: A-hi, B-hi, B-lo for BOTH kk halves
#pragma unroll
        for (int kk = 0; kk < 2; kk++) {
            if constexpr (TN) {
                const uint32_t ak = st + a_fb + kk * 4352;     // 16 k-rows * 272B
                const uint32_t bk = st + b_fb + kk * 2304;     // 16 k-rows * 144B
#pragma unroll
                for (int mi = 0; mi < 4; mi++) LDM4T(Ahf[kk][mi], ak + mi * 32);
#pragma unroll
                for (int p = 0; p < 2; p++) {
                    LDM4T(Bhf[kk][p], bk + p * 32);
                    LDM4T(Blf[kk][p], bk + B_TILE + p * 32);
                }
            } else {
                const uint32_t ak = st + a_fb + kk * 32;
                const uint32_t bk = st + b_fb + kk * 32;
#pragma unroll
                for (int mi = 0; mi < 4; mi++) LDM4(Ahf[kk][mi], ak + mi * 1280);
#pragma unroll
                for (int p = 0; p < 2; p++) {
                    LDM4(Bhf[kk][p], bk + p * 1280);
                    LDM4(Blf[kk][p], bk + B_TILE + p * 1280);
                }
            }
        }

#pragma unroll
        for (int kk = 0; kk < 2; kk++) {
            // A-lo single-buffered: issued before the hh pass, needed only by the lh pass
            if constexpr (TN) {
                const uint32_t ak = st + a_fb + kk * 4352 + A_TILE;
#pragma unroll
                for (int mi = 0; mi < 4; mi++) LDM4T(Alf[mi], ak + mi * 32);
            } else {
                const uint32_t ak = st + a_fb + kk * 32 + A_TILE;
#pragma unroll
                for (int mi = 0; mi < 4; mi++) LDM4(Alf[mi], ak + mi * 1280);
            }
            // pass hh
#pragma unroll
            for (int mi = 0; mi < 4; mi++)
#pragma unroll
                for (int nj = 0; nj < 4; nj++)
                    MMA16816(acc[mi][nj], Ahf[kk][mi], Bhf[kk][nj>>1][nj&1], Bhf[kk][nj>>1][(nj&1)+2]);
            // pass hl
#pragma unroll
            for (int mi = 0; mi < 4; mi++)
#pragma unroll
                for (int nj = 0; nj < 4; nj++)
                    MMA16816(acc[mi][nj], Ahf[kk][mi], Blf[kk][nj>>1][nj&1], Blf[kk][nj>>1][(nj&1)+2]);
            // pass lh
#pragma unroll
            for (int mi = 0; mi < 4; mi++)
#pragma unroll
                for (int nj = 0; nj < 4; nj++)
                    MMA16816(acc[mi][nj], Alf[mi], Bhf[kk][nj>>1][nj&1], Bhf[kk][nj>>1][(nj&1)+2]);
        }
    }

    // epilogue
    const int qr = lid >> 2, qc = (lid & 3) * 2;
    const bool vmode = (n0 >= P.nsplit);
#pragma unroll
    for (int mi = 0; mi < 4; mi++) {
        const int row0 = m0 + wm0 + mi * 16 + qr;
        const int row1 = row0 + 8;
#pragma unroll
        for (int nj = 0; nj < 4; nj++) {
            const int col = n0 + wn0 + nj * 8 + qc;
            float v00 = acc[mi][nj][0] * P.alpha;
            float v01 = acc[mi][nj][1] * P.alpha;
            float v10 = acc[mi][nj][2] * P.alpha;
            float v11 = acc[mi][nj][3] * P.alpha;
            if (vmode) {
                const int c0 = col - P.nsplit;
                if (P.bias) {
                    float b0 = P.bias[c0], b1 = P.bias[c0 + 1];
                    v00 += b0; v01 += b1; v10 += b0; v11 += b1;
                }
                ushort2 h0, l0, h1, l1;
                split2(v00, h0.x, l0.x); split2(v01, h0.y, l0.y);
                split2(v10, h1.x, l1.x); split2(v11, h1.y, l1.y);
                size_t o0 = (size_t)row0 * P.Nc + c0;
                size_t o1 = (size_t)row1 * P.Nc + c0;
                *reinterpret_cast<ushort2*>(P.Ch + o0) = h0;
                *reinterpret_cast<ushort2*>(P.Cl + o0) = l0;
                *reinterpret_cast<ushort2*>(P.Ch + o1) = h1;
                *reinterpret_cast<ushort2*>(P.Cl + o1) = l1;
            } else {
                float* Cb = P.C + (size_t)bz * P.sC;
                float2 a0, a1;
                a0.x = v00; a0.y = v01; a1.x = v10; a1.y = v11;
                *reinterpret_cast<float2*>(Cb + (size_t)row0 * P.Nc + col) = a0;
                *reinterpret_cast<float2*>(Cb + (size_t)row1 * P.Nc + col) = a1;
            }
        }
    }
}

#define NT_SMEM (3*(2*10240 + 2*5120))   // 92160 -> 2 CTAs/SM
#define TN_SMEM (3*(2*8704  + 2*4608))   // 79872 -> 2 CTAs/SM

__global__ void __launch_bounds__(128, 2) gemm_nt(GP P) {
    extern __shared__ __align__(16) char smem[];
    gemm_body<false>(P, blockIdx.x, blockIdx.y, blockIdx.z, smem);
}
__global__ void __launch_bounds__(128, 2) gemm_tn(GP P) {
    extern __shared__ __align__(16) char smem[];
    gemm_body<true>(P, blockIdx.x, blockIdx.y, blockIdx.z, smem);
}

// ---------------- pack kernels ----------------
__global__ __launch_bounds__(256) void pack_weights(const float4* __restrict__ Wc,
                                                    const float4* __restrict__ Wo,
                                                    ushort4* __restrict__ H, ushort4* __restrict__ L)
{
    const long half = (long)Cc * Cc / 4;
    long i = (long)blockIdx.x * 256 + threadIdx.x;
    if (i >= 2 * half) return;
    float4 v = (i < half) ? Wc[i] : Wo[i - half];
    ushort4 h, l;
    split2(v.x, h.x, l.x); split2(v.y, h.y, l.y);
    split2(v.z, h.z, l.z); split2(v.w, h.w, l.w);
    H[i] = h; L[i] = l;
}

__global__ __launch_bounds__(256) void pack_split(const float4* __restrict__ X,
                                                  ushort4* __restrict__ H, ushort4* __restrict__ L, long n4)
{
    long i = (long)blockIdx.x * 256 + threadIdx.x;
    if (i >= n4) return;
    float4 v = X[i];
    ushort4 h, l;
    split2(v.x, h.x, l.x); split2(v.y, h.y, l.y);
    split2(v.z, h.z, l.z); split2(v.w, h.w, l.w);
    H[i] = h; L[i] = l;
}

__global__ __launch_bounds__(256) void pack_bn_relu(const float4* __restrict__ X,
                                                    ushort4* __restrict__ H, ushort4* __restrict__ L,
                                                    const float* __restrict__ g, const float* __restrict__ bb)
{
    long i = (long)blockIdx.x * 256 + threadIdx.x;   // over ROWS1*Cc/4
    float4 v = X[i];
    int ch = (int)((i * 4) % Cc);
    v.x = fmaxf(g[ch+0]*(v.x - g_mu1[ch+0])*g_rs1[ch+0] + bb[ch+0], 0.f);
    v.y = fmaxf(g[ch+1]*(v.y - g_mu1[ch+1])*g_rs1[ch+1] + bb[ch+1], 0.f);
    v.z = fmaxf(g[ch+2]*(v.z - g_mu1[ch+2])*g_rs1[ch+2] + bb[ch+2], 0.f);
    v.w = fmaxf(g[ch+3]*(v.w - g_mu1[ch+3])*g_rs1[ch+3] + bb[ch+3], 0.f);
    ushort4 h, l;
    split2(v.x, h.x, l.x); split2(v.y, h.y, l.y);
    split2(v.z, h.z, l.z); split2(v.w, h.w, l.w);
    H[i] = h; L[i] = l;
}

// ---------------- per-(b,t) column: softmax + K-th-largest radix select -> fp16 hi/lo ----------------
__global__ __launch_bounds__(256) void topk_softmax(const float* __restrict__ kvals,
                                                    ushrt* __restrict__ Wh, ushrt* __restrict__ Wl)
{
    const int b = blockIdx.x >> 9;
    const int t = blockIdx.x & 511;
    const size_t base = ((size_t)b * Tt + t) * Nn;
    const float* col = g_attn + base;
    const int tid = threadIdx.x;
    const int lid = tid & 31, wrp = tid >> 5;
    __shared__ float sh[8];
    __shared__ unsigned hist[256];
    __shared__ unsigned wtot[8];
    __shared__ unsigned s_sel, s_rem;

    float x[4]; unsigned u[4];
    float mx = -3.4e38f;
#pragma unroll
    for (int i = 0; i < 4; i++) {
        x[i] = col[tid + 256 * i];
        mx = fmaxf(mx, x[i]);
        unsigned bits = __float_as_uint(x[i]);
        u[i] = (bits & 0x80000000u) ? ~bits : (bits | 0x80000000u);
    }
    for (int o = 16; o > 0; o >>= 1) mx = fmaxf(mx, __shfl_xor_sync(0xffffffffu, mx, o));
    if (lid == 0) sh[wrp] = mx;
    __syncthreads();
    if (tid == 0) { float m = sh[0]; for (int i = 1; i < 8; i++) m = fmaxf(m, sh[i]); sh[0] = m; }
    __syncthreads();
    mx = sh[0];
    __syncthreads();
    float s = 0.f;
#pragma unroll
    for (int i = 0; i < 4; i++) s += expf(x[i] - mx);
    for (int o = 16; o > 0; o >>= 1) s += __shfl_xor_sync(0xffffffffu, s, o);
    if (lid == 0) sh[wrp] = s;
    __syncthreads();
    if (tid == 0) { float m = 0.f; for (int i = 0; i < 8; i++) m += sh[i]; sh[0] = m; }
    __syncthreads();
    const float inv = 1.f / sh[0];

    int K = (int)rintf((float)Nn * kvals[b]);
    if (K < 0) K = 0;
    if (K > Nn) K = Nn;
    if (K == 0) {
#pragma unroll
        for (int i = 0; i < 4; i++) { Wh[base + tid + 256*i] = 0; Wl[base + tid + 256*i] = 0; }
        return;
    }
    unsigned thr = 0u;
    if (K < Nn) {
        unsigned pref = 0u, rem = (unsigned)K;
        for (int shift = 24; shift >= 0; shift -= 8) {
            hist[tid] = 0u;
            __syncthreads();
            unsigned hm = (shift == 24) ? 0u : (0xFFFFFFFFu << (shift + 8));
#pragma unroll
            for (int i = 0; i < 4; i++)
                if ((u[i] & hm) == pref) atomicAdd(&hist[(u[i] >> shift) & 255u], 1u);
            __syncthreads();
            // inclusive suffix sum via warp shuffles (3 barriers instead of 19)
            unsigned hv = hist[tid];
            unsigned v = hv;
#pragma unroll
            for (int o = 1; o < 32; o <<= 1) {
                unsigned tt = __shfl_down_sync(0xffffffffu, v, o);
                if (lid + o < 32) v += tt;
            }
            if (lid == 0) wtot[wrp] = v;
            __syncthreads();
            unsigned add = 0;
            for (int j = wrp + 1; j < 8; j++) add += wtot[j];
            v += add;                               // suffix sum including hist[tid]
            unsigned nxt = v - hv;                  // suffix sum of tid+1..255
            if (v >= rem && nxt < rem) { s_sel = (unsigned)tid; s_rem = rem - nxt; }
            __syncthreads();
            pref |= (s_sel << shift);
            rem = s_rem;
            __syncthreads();
        }
        thr = pref;
    }
#pragma unroll
    for (int i = 0; i < 4; i++) {
        float w = (u[i] >= thr) ? expf(x[i] - mx) * inv : 0.f;
        ushrt h, l;
        split2(w, h, l);
        Wh[base + tid + 256*i] = h;
        Wl[base + tid + 256*i] = l;
    }
}

// ---------------- BN stats ----------------
__global__ __launch_bounds__(256) void bn_partial(const float* __restrict__ X, float* __restrict__ part)
{
    const int tid = threadIdx.x;
    const float* base = X + (size_t)blockIdx.x * 128 * Cc;
    float s0=0,s1=0,s2=0,q0=0,q1=0,q2=0;
    for (int r = 0; r < 128; r++) {
        const float* row = base + (size_t)r * Cc;
        float a = row[tid], b = row[tid+256], c = row[tid+512];
        s0 += a; q0 = fmaf(a,a,q0);
        s1 += b; q1 = fmaf(b,b,q1);
        s2 += c; q2 = fmaf(c,c,q2);
    }
    float* p = part + (size_t)blockIdx.x * (2*Cc);
    p[tid]    = s0; p[tid+256]    = s1; p[tid+512]    = s2;
    p[Cc+tid] = q0; p[Cc+tid+256] = q1; p[Cc+tid+512] = q2;
}

__global__ void bn_finalize(const float* __restrict__ part, int nblk, float invN,
                            float* __restrict__ mu, float* __restrict__ rs)
{
    int c = blockIdx.x * 256 + threadIdx.x;
    if (c >= Cc) return;
    float s = 0.f, q = 0.f;
    for (int i = 0; i < nblk; i++) {
        s += part[(size_t)i * 2 * Cc + c];
        q += part[(size_t)i * 2 * Cc + Cc + c];
    }
    float m = s * invN;
    mu[c] = m;
    rs[c] = rsqrtf(q * invN - m * m + 1e-5f);
}

__global__ __launch_bounds__(256) void final_apply(float* __restrict__ out, const float* __restrict__ img,
                                                   const float* __restrict__ g, const float* __restrict__ bb)
{
    int i4 = blockIdx.x * 256 + threadIdx.x;
    float4 o = reinterpret_cast<float4*>(out)[i4];
    float4 im = reinterpret_cast<const float4*>(img)[i4];
    int c = (i4 * 4) % Cc;
    o.x = fmaxf(g[c+0]*(o.x - g_mu2[c+0])*g_rs2[c+0] + bb[c+0], 0.f) + im.x;
    o.y = fmaxf(g[c+1]*(o.y - g_mu2[c+1])*g_rs2[c+1] + bb[c+1], 0.f) + im.y;
    o.z = fmaxf(g[c+2]*(o.z - g_mu2[c+2])*g_rs2[c+2] + bb[c+2], 0.f) + im.z;
    o.w = fmaxf(g[c+3]*(o.w - g_mu2[c+3])*g_rs2[c+3] + bb[c+3], 0.f) + im.w;
    reinterpret_cast<float4*>(out)[i4] = o;
}

// ---------------- orchestration ----------------
extern "C" void kernel_launch(void* const* d_in, const int* in_sizes, int n_in,
                              void* d_out, int out_size)
{
    (void)in_sizes; (void)n_in; (void)out_size;
    const float* image = (const float*)d_in[0];
    const float* text  = (const float*)d_in[1];
    const float* kv    = (const float*)d_in[2];
    const float* Wc    = (const float*)d_in[3];
    const float* g1    = (const float*)d_in[5];
    const float* b1    = (const float*)d_in[6];
    const float* Wout  = (const float*)d_in[7];
    const float* bout  = (const float*)d_in[8];
    const float* g2    = (const float*)d_in[9];
    const float* b2    = (const float*)d_in[10];
    float* out = (float*)d_out;

    float *y1, *attn, *p1, *p2, *mu1, *rs1, *mu2, *rs2;
    ushrt *tx_h, *tx_l, *im_h, *im_l, *wcat_h, *wcat_l,
          *e1_h, *e1_l, *v_h, *v_l, *wt_h, *wt_l;
    cudaGetSymbolAddress((void**)&y1,   g_y1);
    cudaGetSymbolAddress((void**)&attn, g_attn);
    cudaGetSymbolAddress((void**)&p1,   g_p1);
    cudaGetSymbolAddress((void**)&p2,   g_p2);
    cudaGetSymbolAddress((void**)&mu1,  g_mu1);
    cudaGetSymbolAddress((void**)&rs1,  g_rs1);
    cudaGetSymbolAddress((void**)&mu2,  g_mu2);
    cudaGetSymbolAddress((void**)&rs2,  g_rs2);
    cudaGetSymbolAddress((void**)&tx_h, p_text_hi);  cudaGetSymbolAddress((void**)&tx_l, p_text_lo);
    cudaGetSymbolAddress((void**)&im_h, p_img_hi);   cudaGetSymbolAddress((void**)&im_l, p_img_lo);
    cudaGetSymbolAddress((void**)&wcat_h, p_Wcat_hi);cudaGetSymbolAddress((void**)&wcat_l, p_Wcat_lo);
    cudaGetSymbolAddress((void**)&e1_h, p_e1_hi);    cudaGetSymbolAddress((void**)&e1_l, p_e1_lo);
    cudaGetSymbolAddress((void**)&v_h,  p_v_hi);     cudaGetSymbolAddress((void**)&v_l,  p_v_lo);
    cudaGetSymbolAddress((void**)&wt_h, p_wt_hi);    cudaGetSymbolAddress((void**)&wt_l, p_wt_lo);

    cudaFuncSetAttribute(gemm_nt, cudaFuncAttributeMaxDynamicSharedMemorySize, NT_SMEM);
    cudaFuncSetAttribute(gemm_tn, cudaFuncAttributeMaxDynamicSharedMemorySize, TN_SMEM);

    const float inv_sqrtC = 0.03608439182435161f;  // 1/sqrt(768)

    // pack text + weights
    pack_split<<<6144, 256>>>((const float4*)text, (ushort4*)tx_h, (ushort4*)tx_l, (long)ROWS1*Cc/4);
    pack_weights<<<1152, 256>>>((const float4*)Wc, (const float4*)Wout, (ushort4*)wcat_h, (ushort4*)wcat_l);

    // merged G1G2, ONE launch: C[8192,1536] = text @ [Wc;Wout]^T
    //   cols 0..767 -> y1 (fp32), cols 768..1535 -> v (split fp16) + bout col bias
    GP Pm = { tx_h, tx_l, wcat_h, wcat_l,
              y1, v_h, v_l,
              Cc, Cc, Cc, Cc, 0, 0, 0, bout, 1.f, Cc };
    gemm_nt<<<dim3(24, 64, 1), 128, NT_SMEM>>>(Pm);

    // pack image
    pack_split<<<12288, 256>>>((const float4*)image, (ushort4*)im_h, (ushort4*)im_l, (long)ROWS2*Cc/4);

    // BN1 stats + fused BN+relu+split-pack of e1
    bn_partial<<<64, 256>>>(y1, p1);
    bn_finalize<<<3, 256>>>(p1, 64, 1.f/(float)ROWS1, mu1, rs1);
    pack_bn_relu<<<6144, 256>>>((const float4*)y1, (ushort4*)e1_h, (ushort4*)e1_l, g1, b1);

    // G3: attn_t[b][512,1024] = (e1[b] @ image[b]^T) / sqrt(C)
    GP P3 = { e1_h, e1_l, im_h, im_l, attn, nullptr, nullptr,
              Cc, Nn, Cc, Cc, (long)Tt*Cc, (long)Nn*Cc, (long)Tt*Nn, nullptr, inv_sqrtC, 1<<30 };
    gemm_nt<<<dim3(16, 4, Bb), 128, NT_SMEM>>>(P3);

    // masked softmax weights -> fp16 hi/lo in [b][t][n]
    topk_softmax<<<Bb*Tt, 256>>>(kv, wt_h, wt_l);

    // G4 (TN): out[b][1024,768] = sum_t w[b][t][n] * v[b][t][c]
    GP P4 = { wt_h, wt_l, v_h, v_l, out, nullptr, nullptr,
              Tt, Cc, Nn, Cc, (long)Tt*Nn, (long)Tt*Cc, (long)Nn*Cc, nullptr, 1.f, 1<<30 };
    gemm_tn<<<dim3(12, 8, Bb), 128, TN_SMEM>>>(P4);

    // BN2 + final
    bn_partial<<<128, 256>>>(out, p2);
    bn_finalize<<<3, 256>>>(p2, 128, 1.f/(float)ROWS2, mu2, rs2);
    final_apply<<<12288, 256>>>(out, image, g2, b2);
}

// round 16
// speedup vs baseline: 1.1507x; 1.0560x over previous
#include <cuda_runtime.h>
#include <cuda_fp16.h>
#include <cstdint>
#include <math.h>

#define Bb 16
#define Nn 1024
#define Tt 512
#define Cc 768
#define ROWS1 (Bb*Tt)   // 8192
#define ROWS2 (Bb*Nn)   // 16384

typedef unsigned short ushrt;

// ---------------- device scratch ----------------
__device__ float g_y1[(size_t)ROWS1*Cc];        // text@Wc^T (pre-BN)
__device__ float g_attn[(size_t)Bb*Tt*Nn];      // attn_t[B,T,N] fp32
__device__ float g_p1[64*2*Cc];
__device__ float g_p2[128*2*Cc];
__device__ float g_mu1[Cc], g_rs1[Cc], g_mu2[Cc], g_rs2[Cc];

// packed fp16 hi/lo operands
__device__ ushrt p_text_hi[(size_t)ROWS1*Cc], p_text_lo[(size_t)ROWS1*Cc];
__device__ ushrt p_img_hi [(size_t)ROWS2*Cc], p_img_lo [(size_t)ROWS2*Cc];
__device__ ushrt p_Wcat_hi[2*Cc*Cc], p_Wcat_lo[2*Cc*Cc];                 // [Wc; Wout] rows
__device__ ushrt p_e1_hi[(size_t)ROWS1*Cc], p_e1_lo[(size_t)ROWS1*Cc];
__device__ ushrt p_v_hi[(size_t)ROWS1*Cc],  p_v_lo[(size_t)ROWS1*Cc];    // v[b][t][c]
__device__ ushrt p_wt_hi[(size_t)Bb*Tt*Nn], p_wt_lo[(size_t)Bb*Tt*Nn];   // w[b][t][n]

// ---------------- helpers ----------------
__device__ __forceinline__ uint32_t smem_u32(const void* p) {
    uint32_t a;
    asm("{ .reg .u64 t; cvta.to.shared.u64 t, %1; cvt.u32.u64 %0, t; }" : "=r"(a) : "l"(p));
    return a;
}
__device__ __forceinline__ void cpa16(uint32_t d, const void* s) {
    asm volatile("cp.async.cg.shared.global [%0], [%1], 16;" :: "r"(d), "l"(s));
}
__device__ __forceinline__ void cpa_commit() { asm volatile("cp.async.commit_group;" ::: "memory"); }
template<int N> __device__ __forceinline__ void cpa_wait() {
    asm volatile("cp.async.wait_group %0;" :: "n"(N) : "memory");
}
#define LDM4(r, addr) \
    asm volatile("ldmatrix.sync.aligned.m8n8.x4.shared.b16 {%0,%1,%2,%3}, [%4];" \
        : "=r"((r)[0]), "=r"((r)[1]), "=r"((r)[2]), "=r"((r)[3]) : "r"(addr))
#define LDM4T(r, addr) \
    asm volatile("ldmatrix.sync.aligned.m8n8.x4.trans.shared.b16 {%0,%1,%2,%3}, [%4];" \
        : "=r"((r)[0]), "=r"((r)[1]), "=r"((r)[2]), "=r"((r)[3]) : "r"(addr))
#define MMA16816(d, a, b0, b1) \
    asm volatile("mma.sync.aligned.m16n8k16.row.col.f32.f16.f16.f32 " \
        "{%0,%1,%2,%3}, {%4,%5,%6,%7}, {%8,%9}, {%0,%1,%2,%3};" \
        : "+f"((d)[0]), "+f"((d)[1]), "+f"((d)[2]), "+f"((d)[3]) \
        : "r"((a)[0]), "r"((a)[1]), "r"((a)[2]), "r"((a)[3]), "r"(b0), "r"(b1))

__device__ __forceinline__ void split2(float x, ushrt& h, ushrt& l) {
    __half hh = __float2half_rn(x);
    float fh = __half2float(hh);
    __half ll = __float2half_rn(x - fh);
    h = *reinterpret_cast<ushrt*>(&hh);
    l = *reinterpret_cast<ushrt*>(&ll);
}

struct GP {
    const ushrt *Ah, *Al, *Bh, *Bl;
    float* C; ushrt *Ch, *Cl;          // fp32 out, or split-fp16 out region (vmode)
    int K, Nc, ldA, ldB;
    long sA, sB, sC;
    const float* bias;                 // column bias, vmode only
    float alpha;
    int nsplit;                        // n0 >= nsplit -> vmode split output
    float* bnPart;                     // if set (and !vmode): per-CTA BN partial sums
    int nby;                           // slot = bz*nby + by
};

// ---------------- fp16x3 MMA GEMM body ----------------
// CTA tile 128(M) x 64(N), BK=32, 128 threads (4 warps 2x2), warp tile 64x32.
// TN=false: A row-major [M][ldA], B row-major [N][ldB].
// TN=true:  A K-major [K][ldA], B K-major [K][ldB] (both trans-loaded).
// 3-stage cp.async pipeline, ONE barrier per chunk, fragment software pipeline.
// Optional fused BN partial reduction over the CTA's 128 rows (deterministic slots).
template<bool TN>
__device__ __forceinline__ void gemm_body(const GP& P, int bx, int by, int bz, char* smem)
{
    constexpr int A_TILE = TN ? 8704 : 10240;   // TN: [32][136]; NT: [128][40]
    constexpr int B_TILE = TN ? 4608 : 5120;    // TN: [32][72];  NT: [64][40]
    constexpr int STAGE  = 2*A_TILE + 2*B_TILE;
    const int tid = threadIdx.x, wid = tid >> 5, lid = tid & 31;
    const int m0 = by * 128, n0 = bx * 64;
    const int K = P.K, nk = K >> 5, ldA = P.ldA, ldB = P.ldB;
    const uint32_t sb = smem_u32(smem);

    const ushrt *gAh, *gAl, *gBh, *gBl;
    if constexpr (TN) {
        gAh = P.Ah + (size_t)bz * P.sA + m0;
        gAl = P.Al + (size_t)bz * P.sA + m0;
        gBh = P.Bh + (size_t)bz * P.sB + n0;
        gBl = P.Bl + (size_t)bz * P.sB + n0;
    } else {
        gAh = P.Ah + (size_t)bz * P.sA + (size_t)m0 * ldA;
        gAl = P.Al + (size_t)bz * P.sA + (size_t)m0 * ldA;
        gBh = P.Bh + (size_t)bz * P.sB + (size_t)n0 * ldB;
        gBl = P.Bl + (size_t)bz * P.sB + (size_t)n0 * ldB;
    }

    uint32_t a_sm[4]; int a_g[4];
    uint32_t b_sm[2]; int b_g[2];
#pragma unroll
    for (int j = 0; j < 4; j++) {
        int i = tid + 128 * j;
        if constexpr (TN) { int r = i >> 4, c8 = (i & 15) * 8; a_sm[j] = (uint32_t)(r * 272 + c8 * 2); a_g[j] = r * ldA + c8; }
        else              { int r = i >> 2, c8 = (i & 3) * 8;  a_sm[j] = (uint32_t)(r * 80 + c8 * 2);  a_g[j] = r * ldA + c8; }
    }
#pragma unroll
    for (int j = 0; j < 2; j++) {
        int i = tid + 128 * j;
        if constexpr (TN) { int r = i >> 3, c8 = (i & 7) * 8; b_sm[j] = (uint32_t)(r * 144 + c8 * 2); b_g[j] = r * ldB + c8; }
        else              { int r = i >> 2, c8 = (i & 3) * 8; b_sm[j] = (uint32_t)(r * 80 + c8 * 2);  b_g[j] = r * ldB + c8; }
    }

    auto load_chunk = [&](int c, int s) {
        uint32_t ds = sb + (uint32_t)s * STAGE;
        size_t aoff = TN ? (size_t)c * 32 * ldA : (size_t)c * 32;
        size_t boff = TN ? (size_t)c * 32 * ldB : (size_t)c * 32;
#pragma unroll
        for (int j = 0; j < 4; j++) {
            cpa16(ds + a_sm[j],          gAh + aoff + a_g[j]);
            cpa16(ds + A_TILE + a_sm[j], gAl + aoff + a_g[j]);
        }
#pragma unroll
        for (int j = 0; j < 2; j++) {
            cpa16(ds + 2*A_TILE + b_sm[j],          gBh + boff + b_g[j]);
            cpa16(ds + 2*A_TILE + B_TILE + b_sm[j], gBl + boff + b_g[j]);
        }
    };

    const int wm0 = (wid >> 1) * 64, wn0 = (wid & 1) * 32;
    uint32_t a_fb, b_fb;
    if constexpr (TN) {
        int k_off = (lid & 7) + ((lid >> 4) << 3);
        int x_off = ((lid >> 3) & 1) << 3;
        a_fb = (uint32_t)(k_off * 272 + (wm0 + x_off) * 2);
        b_fb = (uint32_t)(2*A_TILE + k_off * 144 + (wn0 + x_off) * 2);
    } else {
        a_fb = (uint32_t)(((wm0 + (lid & 15)) * 40 + (lid >> 4) * 8) * 2);
        b_fb = (uint32_t)(2*A_TILE + ((wn0 + (lid & 15)) * 40 + (lid >> 4) * 8) * 2);
    }

    float acc[4][4][4] = {};

    load_chunk(0, 0);
    cpa_commit();
    load_chunk(1, 1);
    cpa_commit();

    for (int c = 0; c < nk; c++) {
        cpa_wait<1>();
        __syncthreads();
        if (c + 2 < nk) load_chunk(c + 2, (c + 2) % 3);
        cpa_commit();

        const uint32_t st = sb + (uint32_t)(c % 3) * STAGE;
        uint32_t Ahf[2][4][4], Bhf[2][2][4], Blf[2][2][4], Alf[4][4];

#pragma unroll
        for (int kk = 0; kk < 2; kk++) {
            if constexpr (TN) {
                const uint32_t ak = st + a_fb + kk * 4352;
                const uint32_t bk = st + b_fb + kk * 2304;
#pragma unroll
                for (int mi = 0; mi < 4; mi++) LDM4T(Ahf[kk][mi], ak + mi * 32);
#pragma unroll
                for (int p = 0; p < 2; p++) {
                    LDM4T(Bhf[kk][p], bk + p * 32);
                    LDM4T(Blf[kk][p], bk + B_TILE + p * 32);
                }
            } else {
                const uint32_t ak = st + a_fb + kk * 32;
                const uint32_t bk = st + b_fb + kk * 32;
#pragma unroll
                for (int mi = 0; mi < 4; mi++) LDM4(Ahf[kk][mi], ak + mi * 1280);
#pragma unroll
                for (int p = 0; p < 2; p++) {
                    LDM4(Bhf[kk][p], bk + p * 1280);
                    LDM4(Blf[kk][p], bk + B_TILE + p * 1280);
                }
            }
        }

#pragma unroll
        for (int kk = 0; kk < 2; kk++) {
            if constexpr (TN) {
                const uint32_t ak = st + a_fb + kk * 4352 + A_TILE;
#pragma unroll
                for (int mi = 0; mi < 4; mi++) LDM4T(Alf[mi], ak + mi * 32);
            } else {
                const uint32_t ak = st + a_fb + kk * 32 + A_TILE;
#pragma unroll
                for (int mi = 0; mi < 4; mi++) LDM4(Alf[mi], ak + mi * 1280);
            }
#pragma unroll
            for (int mi = 0; mi < 4; mi++)
#pragma unroll
                for (int nj = 0; nj < 4; nj++)
                    MMA16816(acc[mi][nj], Ahf[kk][mi], Bhf[kk][nj>>1][nj&1], Bhf[kk][nj>>1][(nj&1)+2]);
#pragma unroll
            for (int mi = 0; mi < 4; mi++)
#pragma unroll
                for (int nj = 0; nj < 4; nj++)
                    MMA16816(acc[mi][nj], Ahf[kk][mi], Blf[kk][nj>>1][nj&1], Blf[kk][nj>>1][(nj&1)+2]);
#pragma unroll
            for (int mi = 0; mi < 4; mi++)
#pragma unroll
                for (int nj = 0; nj < 4; nj++)
                    MMA16816(acc[mi][nj], Alf[mi], Bhf[kk][nj>>1][nj&1], Bhf[kk][nj>>1][(nj&1)+2]);
        }
    }

    // epilogue
    const int qr = lid >> 2, qc = (lid & 3) * 2;
    const bool vmode = (n0 >= P.nsplit);
    const bool doBN = (P.bnPart != nullptr) && !vmode;
    float colS[8], colQ[8];
#pragma unroll
    for (int j = 0; j < 8; j++) { colS[j] = 0.f; colQ[j] = 0.f; }

#pragma unroll
    for (int mi = 0; mi < 4; mi++) {
        const int row0 = m0 + wm0 + mi * 16 + qr;
        const int row1 = row0 + 8;
#pragma unroll
        for (int nj = 0; nj < 4; nj++) {
            const int col = n0 + wn0 + nj * 8 + qc;
            float v00 = acc[mi][nj][0] * P.alpha;
            float v01 = acc[mi][nj][1] * P.alpha;
            float v10 = acc[mi][nj][2] * P.alpha;
            float v11 = acc[mi][nj][3] * P.alpha;
            if (vmode) {
                const int c0 = col - P.nsplit;
                if (P.bias) {
                    float b0 = P.bias[c0], b1 = P.bias[c0 + 1];
                    v00 += b0; v01 += b1; v10 += b0; v11 += b1;
                }
                ushort2 h0, l0, h1, l1;
                split2(v00, h0.x, l0.x); split2(v01, h0.y, l0.y);
                split2(v10, h1.x, l1.x); split2(v11, h1.y, l1.y);
                size_t o0 = (size_t)row0 * P.Nc + c0;
                size_t o1 = (size_t)row1 * P.Nc + c0;
                *reinterpret_cast<ushort2*>(P.Ch + o0) = h0;
                *reinterpret_cast<ushort2*>(P.Cl + o0) = l0;
                *reinterpret_cast<ushort2*>(P.Ch + o1) = h1;
                *reinterpret_cast<ushort2*>(P.Cl + o1) = l1;
            } else {
                float* Cb = P.C + (size_t)bz * P.sC;
                float2 a0, a1;
                a0.x = v00; a0.y = v01; a1.x = v10; a1.y = v11;
                *reinterpret_cast<float2*>(Cb + (size_t)row0 * P.Nc + col) = a0;
                *reinterpret_cast<float2*>(Cb + (size_t)row1 * P.Nc + col) = a1;
                if (doBN) {
                    colS[nj*2+0] += v00 + v10;
                    colS[nj*2+1] += v01 + v11;
                    colQ[nj*2+0] += v00*v00 + v10*v10;
                    colQ[nj*2+1] += v01*v01 + v11*v11;
                }
            }
        }
    }

    if (doBN) {
        // reduce across qr lanes (same lid&3 group: lanes differ in bits 2..4)
#pragma unroll
        for (int o = 4; o <= 16; o <<= 1) {
#pragma unroll
            for (int j = 0; j < 8; j++) {
                colS[j] += __shfl_xor_sync(0xffffffffu, colS[j], o);
                colQ[j] += __shfl_xor_sync(0xffffffffu, colQ[j], o);
            }
        }
        float* buf = (float*)smem;          // [2][64][2] floats = 1KB
        __syncthreads();                    // mainloop smem reads done everywhere
        if (lid < 4) {
            const int wm_idx = wid >> 1;    // 0: rows 0-63, 1: rows 64-127
#pragma unroll
            for (int nj = 0; nj < 4; nj++) {
#pragma unroll
                for (int e = 0; e < 2; e++) {
                    int cl = wn0 + nj * 8 + qc + e;      // 0..63
                    buf[(wm_idx * 64 + cl) * 2 + 0] = colS[nj*2+e];
                    buf[(wm_idx * 64 + cl) * 2 + 1] = colQ[nj*2+e];
                }
            }
        }
        __syncthreads();
        if (tid < 64) {
            float s = buf[tid*2+0] + buf[(64+tid)*2+0];
            float q = buf[tid*2+1] + buf[(64+tid)*2+1];
            int slot = bz * P.nby + by;
            float* p = P.bnPart + (size_t)slot * 2 * Cc;
            p[n0 + tid]      = s;
            p[Cc + n0 + tid] = q;
        }
    }
}

#define NT_SMEM (3*(2*10240 + 2*5120))   // 92160 -> 2 CTAs/SM
#define TN_SMEM (3*(2*8704  + 2*4608))   // 79872 -> 2 CTAs/SM

__global__ void __launch_bounds__(128, 2) gemm_nt(GP P) {
    extern __shared__ __align__(16) char smem[];
    gemm_body<false>(P, blockIdx.x, blockIdx.y, blockIdx.z, smem);
}
__global__ void __launch_bounds__(128, 2) gemm_tn(GP P) {
    extern __shared__ __align__(16) char smem[];
    gemm_body<true>(P, blockIdx.x, blockIdx.y, blockIdx.z, smem);
}

// ---------------- pack kernels ----------------
__global__ __launch_bounds__(256) void pack_weights(const float4* __restrict__ Wc,
                                                    const float4* __restrict__ Wo,
                                                    ushort4* __restrict__ H, ushort4* __restrict__ L)
{
    const long half = (long)Cc * Cc / 4;
    long i = (long)blockIdx.x * 256 + threadIdx.x;
    if (i >= 2 * half) return;
    float4 v = (i < half) ? Wc[i] : Wo[i - half];
    ushort4 h, l;
    split2(v.x, h.x, l.x); split2(v.y, h.y, l.y);
    split2(v.z, h.z, l.z); split2(v.w, h.w, l.w);
    H[i] = h; L[i] = l;
}

__global__ __launch_bounds__(256) void pack_split(const float4* __restrict__ X,
                                                  ushort4* __restrict__ H, ushort4* __restrict__ L, long n4)
{
    long i = (long)blockIdx.x * 256 + threadIdx.x;
    if (i >= n4) return;
    float4 v = X[i];
    ushort4 h, l;
    split2(v.x, h.x, l.x); split2(v.y, h.y, l.y);
    split2(v.z, h.z, l.z); split2(v.w, h.w, l.w);
    H[i] = h; L[i] = l;
}

__global__ __launch_bounds__(256) void pack_bn_relu(const float4* __restrict__ X,
                                                    ushort4* __restrict__ H, ushort4* __restrict__ L,
                                                    const float* __restrict__ g, const float* __restrict__ bb)
{
    long i = (long)blockIdx.x * 256 + threadIdx.x;   // over ROWS1*Cc/4
    float4 v = X[i];
    int ch = (int)((i * 4) % Cc);
    v.x = fmaxf(g[ch+0]*(v.x - g_mu1[ch+0])*g_rs1[ch+0] + bb[ch+0], 0.f);
    v.y = fmaxf(g[ch+1]*(v.y - g_mu1[ch+1])*g_rs1[ch+1] + bb[ch+1], 0.f);
    v.z = fmaxf(g[ch+2]*(v.z - g_mu1[ch+2])*g_rs1[ch+2] + bb[ch+2], 0.f);
    v.w = fmaxf(g[ch+3]*(v.w - g_mu1[ch+3])*g_rs1[ch+3] + bb[ch+3], 0.f);
    ushort4 h, l;
    split2(v.x, h.x, l.x); split2(v.y, h.y, l.y);
    split2(v.z, h.z, l.z); split2(v.w, h.w, l.w);
    H[i] = h; L[i] = l;
}

// ---------------- per-(b,t) column: softmax + K-th-largest radix select -> fp16 hi/lo ----------------
__global__ __launch_bounds__(256) void topk_softmax(const float* __restrict__ kvals,
                                                    ushrt* __restrict__ Wh, ushrt* __restrict__ Wl)
{
    const int b = blockIdx.x >> 9;
    const int t = blockIdx.x & 511;
    const size_t base = ((size_t)b * Tt + t) * Nn;
    const float* col = g_attn + base;
    const int tid = threadIdx.x;
    const int lid = tid & 31, wrp = tid >> 5;
    __shared__ float sh[8];
    __shared__ unsigned hist[256];
    __shared__ unsigned wtot[8];
    __shared__ unsigned s_sel, s_rem;

    float x[4]; unsigned u[4];
    float mx = -3.4e38f;
#pragma unroll
    for (int i = 0; i < 4; i++) {
        x[i] = col[tid + 256 * i];
        mx = fmaxf(mx, x[i]);
        unsigned bits = __float_as_uint(x[i]);
        u[i] = (bits & 0x80000000u) ? ~bits : (bits | 0x80000000u);
    }
    for (int o = 16; o > 0; o >>= 1) mx = fmaxf(mx, __shfl_xor_sync(0xffffffffu, mx, o));
    if (lid == 0) sh[wrp] = mx;
    __syncthreads();
    if (tid == 0) { float m = sh[0]; for (int i = 1; i < 8; i++) m = fmaxf(m, sh[i]); sh[0] = m; }
    __syncthreads();
    mx = sh[0];
    __syncthreads();
    float s = 0.f;
#pragma unroll
    for (int i = 0; i < 4; i++) s += expf(x[i] - mx);
    for (int o = 16; o > 0; o >>= 1) s += __shfl_xor_sync(0xffffffffu, s, o);
    if (lid == 0) sh[wrp] = s;
    __syncthreads();
    if (tid == 0) { float m = 0.f; for (int i = 0; i < 8; i++) m += sh[i]; sh[0] = m; }
    __syncthreads();
    const float inv = 1.f / sh[0];

    int K = (int)rintf((float)Nn * kvals[b]);
    if (K < 0) K = 0;
    if (K > Nn) K = Nn;
    if (K == 0) {
#pragma unroll
        for (int i = 0; i < 4; i++) { Wh[base + tid + 256*i] = 0; Wl[base + tid + 256*i] = 0; }
        return;
    }
    unsigned thr = 0u;
    if (K < Nn) {
        unsigned pref = 0u, rem = (unsigned)K;
        for (int shift = 24; shift >= 0; shift -= 8) {
            hist[tid] = 0u;
            __syncthreads();
            unsigned hm = (shift == 24) ? 0u : (0xFFFFFFFFu << (shift + 8));
#pragma unroll
            for (int i = 0; i < 4; i++)
                if ((u[i] & hm) == pref) atomicAdd(&hist[(u[i] >> shift) & 255u], 1u);
            __syncthreads();
            unsigned hv = hist[tid];
            unsigned v = hv;
#pragma unroll
            for (int o = 1; o < 32; o <<= 1) {
                unsigned tt = __shfl_down_sync(0xffffffffu, v, o);
                if (lid + o < 32) v += tt;
            }
            if (lid == 0) wtot[wrp] = v;
            __syncthreads();
            unsigned add = 0;
            for (int j = wrp + 1; j < 8; j++) add += wtot[j];
            v += add;
            unsigned nxt = v - hv;
            if (v >= rem && nxt < rem) { s_sel = (unsigned)tid; s_rem = rem - nxt; }
            __syncthreads();
            pref |= (s_sel << shift);
            rem = s_rem;
            __syncthreads();
        }
        thr = pref;
    }
#pragma unroll
    for (int i = 0; i < 4; i++) {
        float w = (u[i] >= thr) ? expf(x[i] - mx) * inv : 0.f;
        ushrt h, l;
        split2(w, h, l);
        Wh[base + tid + 256*i] = h;
        Wl[base + tid + 256*i] = l;
    }
}

// ---------------- BN finalize ----------------
__global__ void bn_finalize(const float* __restrict__ part, int nblk, float invN,
                            float* __restrict__ mu, float* __restrict__ rs)
{
    int c = blockIdx.x * 256 + threadIdx.x;
    if (c >= Cc) return;
    float s = 0.f, q = 0.f;
    for (int i = 0; i < nblk; i++) {
        s += part[(size_t)i * 2 * Cc + c];
        q += part[(size_t)i * 2 * Cc + Cc + c];
    }
    float m = s * invN;
    mu[c] = m;
    rs[c] = rsqrtf(q * invN - m * m + 1e-5f);
}

__global__ __launch_bounds__(256) void final_apply(float* __restrict__ out, const float* __restrict__ img,
                                                   const float* __restrict__ g, const float* __restrict__ bb)
{
    int i4 = blockIdx.x * 256 + threadIdx.x;
    float4 o = reinterpret_cast<float4*>(out)[i4];
    float4 im = reinterpret_cast<const float4*>(img)[i4];
    int c = (i4 * 4) % Cc;
    o.x = fmaxf(g[c+0]*(o.x - g_mu2[c+0])*g_rs2[c+0] + bb[c+0], 0.f) + im.x;
    o.y = fmaxf(g[c+1]*(o.y - g_mu2[c+1])*g_rs2[c+1] + bb[c+1], 0.f) + im.y;
    o.z = fmaxf(g[c+2]*(o.z - g_mu2[c+2])*g_rs2[c+2] + bb[c+2], 0.f) + im.z;
    o.w = fmaxf(g[c+3]*(o.w - g_mu2[c+3])*g_rs2[c+3] + bb[c+3], 0.f) + im.w;
    reinterpret_cast<float4*>(out)[i4] = o;
}

// ---------------- orchestration ----------------
extern "C" void kernel_launch(void* const* d_in, const int* in_sizes, int n_in,
                              void* d_out, int out_size)
{
    (void)in_sizes; (void)n_in; (void)out_size;
    const float* image = (const float*)d_in[0];
    const float* text  = (const float*)d_in[1];
    const float* kv    = (const float*)d_in[2];
    const float* Wc    = (const float*)d_in[3];
    const float* g1    = (const float*)d_in[5];
    const float* b1    = (const float*)d_in[6];
    const float* Wout  = (const float*)d_in[7];
    const float* bout  = (const float*)d_in[8];
    const float* g2    = (const float*)d_in[9];
    const float* b2    = (const float*)d_in[10];
    float* out = (float*)d_out;

    float *y1, *attn, *p1, *p2, *mu1, *rs1, *mu2, *rs2;
    ushrt *tx_h, *tx_l, *im_h, *im_l, *wcat_h, *wcat_l,
          *e1_h, *e1_l, *v_h, *v_l, *wt_h, *wt_l;
    cudaGetSymbolAddress((void**)&y1,   g_y1);
    cudaGetSymbolAddress((void**)&attn, g_attn);
    cudaGetSymbolAddress((void**)&p1,   g_p1);
    cudaGetSymbolAddress((void**)&p2,   g_p2);
    cudaGetSymbolAddress((void**)&mu1,  g_mu1);
    cudaGetSymbolAddress((void**)&rs1,  g_rs1);
    cudaGetSymbolAddress((void**)&mu2,  g_mu2);
    cudaGetSymbolAddress((void**)&rs2,  g_rs2);
    cudaGetSymbolAddress((void**)&tx_h, p_text_hi);  cudaGetSymbolAddress((void**)&tx_l, p_text_lo);
    cudaGetSymbolAddress((void**)&im_h, p_img_hi);   cudaGetSymbolAddress((void**)&im_l, p_img_lo);
    cudaGetSymbolAddress((void**)&wcat_h, p_Wcat_hi);cudaGetSymbolAddress((void**)&wcat_l, p_Wcat_lo);
    cudaGetSymbolAddress((void**)&e1_h, p_e1_hi);    cudaGetSymbolAddress((void**)&e1_l, p_e1_lo);
    cudaGetSymbolAddress((void**)&v_h,  p_v_hi);     cudaGetSymbolAddress((void**)&v_l,  p_v_lo);
    cudaGetSymbolAddress((void**)&wt_h, p_wt_hi);    cudaGetSymbolAddress((void**)&wt_l, p_wt_lo);

    cudaFuncSetAttribute(gemm_nt, cudaFuncAttributeMaxDynamicSharedMemorySize, NT_SMEM);
    cudaFuncSetAttribute(gemm_tn, cudaFuncAttributeMaxDynamicSharedMemorySize, TN_SMEM);

    const float inv_sqrtC = 0.03608439182435161f;  // 1/sqrt(768)

    // pack text + weights
    pack_split<<<6144, 256>>>((const float4*)text, (ushort4*)tx_h, (ushort4*)tx_l, (long)ROWS1*Cc/4);
    pack_weights<<<1152, 256>>>((const float4*)Wc, (const float4*)Wout, (ushort4*)wcat_h, (ushort4*)wcat_l);

    // merged G1G2 (one launch): C[8192,1536] = text @ [Wc;Wout]^T
    //   cols 0..767 -> y1 (fp32, + fused BN1 partials), cols 768..1535 -> v (split fp16) + bout bias
    GP Pm = { tx_h, tx_l, wcat_h, wcat_l,
              y1, v_h, v_l,
              Cc, Cc, Cc, Cc, 0, 0, 0, bout, 1.f, Cc, p1, 64 };
    gemm_nt<<<dim3(24, 64, 1), 128, NT_SMEM>>>(Pm);

    // pack image
    pack_split<<<12288, 256>>>((const float4*)image, (ushort4*)im_h, (ushort4*)im_l, (long)ROWS2*Cc/4);

    // BN1 finalize (partials fused into G1G2 epilogue) + fused BN+relu+split-pack of e1
    bn_finalize<<<3, 256>>>(p1, 64, 1.f/(float)ROWS1, mu1, rs1);
    pack_bn_relu<<<6144, 256>>>((const float4*)y1, (ushort4*)e1_h, (ushort4*)e1_l, g1, b1);

    // G3: attn_t[b][512,1024] = (e1[b] @ image[b]^T) / sqrt(C)
    GP P3 = { e1_h, e1_l, im_h, im_l, attn, nullptr, nullptr,
              Cc, Nn, Cc, Cc, (long)Tt*Cc, (long)Nn*Cc, (long)Tt*Nn, nullptr, inv_sqrtC, 1<<30,
              nullptr, 0 };
    gemm_nt<<<dim3(16, 4, Bb), 128, NT_SMEM>>>(P3);

    // masked softmax weights -> fp16 hi/lo in [b][t][n]
    topk_softmax<<<Bb*Tt, 256>>>(kv, wt_h, wt_l);

    // G4 (TN): out[b][1024,768] = sum_t w[b][t][n] * v[b][t][c]  + fused BN2 partials
    GP P4 = { wt_h, wt_l, v_h, v_l, out, nullptr, nullptr,
              Tt, Cc, Nn, Cc, (long)Tt*Nn, (long)Tt*Cc, (long)Nn*Cc, nullptr, 1.f, 1<<30,
              p2, 8 };
    gemm_tn<<<dim3(12, 8, Bb), 128, TN_SMEM>>>(P4);

    // BN2 finalize + final
    bn_finalize<<<3, 256>>>(p2, 128, 1.f/(float)ROWS2, mu2, rs2);
    final_apply<<<12288, 256>>>(out, image, g2, b2);
}

// round 17
// speedup vs baseline: 1.1920x; 1.0359x over previous
#include <cuda_runtime.h>
#include <cuda_fp16.h>
#include <cstdint>
#include <math.h>

#define Bb 16
#define Nn 1024
#define Tt 512
#define Cc 768
#define ROWS1 (Bb*Tt)   // 8192
#define ROWS2 (Bb*Nn)   // 16384

typedef unsigned short ushrt;

// ---------------- device scratch ----------------
__device__ float g_y1[(size_t)ROWS1*Cc];        // text@Wc^T (pre-BN)
__device__ float g_attn[(size_t)Bb*Tt*Nn];      // attn_t[B,T,N] fp32
__device__ float g_p1[64*2*Cc];
__device__ float g_p2[128*2*Cc];
__device__ float g_mu1[Cc], g_rs1[Cc], g_mu2[Cc], g_rs2[Cc];

// packed fp16 hi/lo operands
__device__ ushrt p_text_hi[(size_t)ROWS1*Cc], p_text_lo[(size_t)ROWS1*Cc];
__device__ ushrt p_img_hi [(size_t)ROWS2*Cc], p_img_lo [(size_t)ROWS2*Cc];
__device__ ushrt p_Wcat_hi[2*Cc*Cc], p_Wcat_lo[2*Cc*Cc];                 // [Wc; Wout] rows
__device__ ushrt p_e1_hi[(size_t)ROWS1*Cc], p_e1_lo[(size_t)ROWS1*Cc];
__device__ ushrt p_v_hi[(size_t)ROWS1*Cc],  p_v_lo[(size_t)ROWS1*Cc];    // v[b][t][c]
__device__ ushrt p_wt_hi[(size_t)Bb*Tt*Nn], p_wt_lo[(size_t)Bb*Tt*Nn];   // w[b][t][n]

// ---------------- helpers ----------------
__device__ __forceinline__ uint32_t smem_u32(const void* p) {
    uint32_t a;
    asm("{ .reg .u64 t; cvta.to.shared.u64 t, %1; cvt.u32.u64 %0, t; }" : "=r"(a) : "l"(p));
    return a;
}
__device__ __forceinline__ void cpa16(uint32_t d, const void* s) {
    asm volatile("cp.async.cg.shared.global [%0], [%1], 16;" :: "r"(d), "l"(s));
}
__device__ __forceinline__ void cpa_commit() { asm volatile("cp.async.commit_group;" ::: "memory"); }
template<int N> __device__ __forceinline__ void cpa_wait() {
    asm volatile("cp.async.wait_group %0;" :: "n"(N) : "memory");
}
#define LDM4(r, addr) \
    asm volatile("ldmatrix.sync.aligned.m8n8.x4.shared.b16 {%0,%1,%2,%3}, [%4];" \
        : "=r"((r)[0]), "=r"((r)[1]), "=r"((r)[2]), "=r"((r)[3]) : "r"(addr))
#define LDM4T(r, addr) \
    asm volatile("ldmatrix.sync.aligned.m8n8.x4.trans.shared.b16 {%0,%1,%2,%3}, [%4];" \
        : "=r"((r)[0]), "=r"((r)[1]), "=r"((r)[2]), "=r"((r)[3]) : "r"(addr))
#define MMA16816(d, a, b0, b1) \
    asm volatile("mma.sync.aligned.m16n8k16.row.col.f32.f16.f16.f32 " \
        "{%0,%1,%2,%3}, {%4,%5,%6,%7}, {%8,%9}, {%0,%1,%2,%3};" \
        : "+f"((d)[0]), "+f"((d)[1]), "+f"((d)[2]), "+f"((d)[3]) \
        : "r"((a)[0]), "r"((a)[1]), "r"((a)[2]), "r"((a)[3]), "r"(b0), "r"(b1))

__device__ __forceinline__ void split2(float x, ushrt& h, ushrt& l) {
    __half hh = __float2half_rn(x);
    float fh = __half2float(hh);
    __half ll = __float2half_rn(x - fh);
    h = *reinterpret_cast<ushrt*>(&hh);
    l = *reinterpret_cast<ushrt*>(&ll);
}

struct GP {
    const ushrt *Ah, *Al, *Bh, *Bl;
    float* C; ushrt *Ch, *Cl;          // fp32 out, or split-fp16 out region (vmode)
    int K, Nc, ldA, ldB;
    long sA, sB, sC;
    const float* bias;                 // column bias, vmode only
    float alpha;
    int nsplit;                        // n0 >= nsplit -> vmode split output
    float* bnPart;                     // if set (and !vmode): per-CTA BN partial sums
    int nby;                           // slot = bz*nby + by
};

// ---------------- fp16x3 MMA GEMM body ----------------
// CTA tile 128(M) x 128(N), BK=32, 128 threads (4 warps 2x2), warp tile 64x64.
// TN=false: A row-major [M][ldA], B row-major [N][ldB].
// TN=true:  A K-major [K][ldA], B K-major [K][ldB] (both trans-loaded).
// 2-stage cp.async double buffer, 2 CTAs/SM. 6 MMA per LDSM (was 4) to relieve
// the smem crossbar, which the R16 accounting showed to be co-binding.
template<bool TN>
__device__ __forceinline__ void gemm_body(const GP& P, int bx, int by, int bz, char* smem)
{
    constexpr int A_TILE = TN ? 8704 : 10240;   // TN: [32][136]; NT: [128][40]
    constexpr int B_TILE = TN ? 8704 : 10240;   // TN: [32][136]; NT: [128][40]
    constexpr int STAGE  = 2*A_TILE + 2*B_TILE;
    const int tid = threadIdx.x, wid = tid >> 5, lid = tid & 31;
    const int m0 = by * 128, n0 = bx * 128;
    const int K = P.K, nk = K >> 5, ldA = P.ldA, ldB = P.ldB;
    const uint32_t sb = smem_u32(smem);

    const ushrt *gAh, *gAl, *gBh, *gBl;
    if constexpr (TN) {
        gAh = P.Ah + (size_t)bz * P.sA + m0;
        gAl = P.Al + (size_t)bz * P.sA + m0;
        gBh = P.Bh + (size_t)bz * P.sB + n0;
        gBl = P.Bl + (size_t)bz * P.sB + n0;
    } else {
        gAh = P.Ah + (size_t)bz * P.sA + (size_t)m0 * ldA;
        gAl = P.Al + (size_t)bz * P.sA + (size_t)m0 * ldA;
        gBh = P.Bh + (size_t)bz * P.sB + (size_t)n0 * ldB;
        gBl = P.Bl + (size_t)bz * P.sB + (size_t)n0 * ldB;
    }

    // 512 16B-chunks per tile; 4 per thread (same mapping for A and B)
    uint32_t a_sm[4]; int a_g[4];
    uint32_t b_sm[4]; int b_g[4];
#pragma unroll
    for (int j = 0; j < 4; j++) {
        int i = tid + 128 * j;
        if constexpr (TN) {
            int r = i >> 4, c8 = (i & 15) * 8;          // 32 k-rows x 128 cols
            a_sm[j] = (uint32_t)(r * 272 + (i & 15) * 16); a_g[j] = r * ldA + c8;
            b_sm[j] = a_sm[j];                             b_g[j] = r * ldB + c8;
        } else {
            int r = i >> 2, c8 = (i & 3) * 8;           // 128 rows x 32 k
            a_sm[j] = (uint32_t)(r * 80 + (i & 3) * 16);  a_g[j] = r * ldA + c8;
            b_sm[j] = a_sm[j];                            b_g[j] = r * ldB + c8;
        }
    }

    auto load_chunk = [&](int c, int s) {
        uint32_t ds = sb + (uint32_t)s * STAGE;
        size_t aoff = TN ? (size_t)c * 32 * ldA : (size_t)c * 32;
        size_t boff = TN ? (size_t)c * 32 * ldB : (size_t)c * 32;
#pragma unroll
        for (int j = 0; j < 4; j++) {
            cpa16(ds + a_sm[j],                     gAh + aoff + a_g[j]);
            cpa16(ds + A_TILE + a_sm[j],            gAl + aoff + a_g[j]);
            cpa16(ds + 2*A_TILE + b_sm[j],          gBh + boff + b_g[j]);
            cpa16(ds + 2*A_TILE + B_TILE + b_sm[j], gBl + boff + b_g[j]);
        }
    };

    const int wm0 = (wid >> 1) * 64, wn0 = (wid & 1) * 64;
    uint32_t a_fb, b_fb;
    if constexpr (TN) {
        int k_off = (lid & 7) + ((lid >> 4) << 3);
        int x_off = ((lid >> 3) & 1) << 3;
        a_fb = (uint32_t)(k_off * 272 + (wm0 + x_off) * 2);
        b_fb = (uint32_t)(2*A_TILE + k_off * 272 + (wn0 + x_off) * 2);
    } else {
        a_fb = (uint32_t)(((wm0 + (lid & 15)) * 40 + (lid >> 4) * 8) * 2);
        b_fb = (uint32_t)(2*A_TILE + ((wn0 + (lid & 15)) * 40 + (lid >> 4) * 8) * 2);
    }

    float acc[4][8][4] = {};

    load_chunk(0, 0);
    cpa_commit();

    for (int c = 0; c < nk; c++) {
        if (c + 1 < nk) {
            load_chunk(c + 1, (c + 1) & 1);
            cpa_commit();
            cpa_wait<1>();
        } else {
            cpa_wait<0>();
        }
        __syncthreads();

        const uint32_t st = sb + (uint32_t)(c & 1) * STAGE;
#pragma unroll
        for (int kk = 0; kk < 2; kk++) {
            uint32_t Ahf[4][4], Alf[4][4], Bhf[4][4], Blf[4][4];
            if constexpr (TN) {
                const uint32_t ak = st + a_fb + kk * 4352;     // 16 k-rows * 272B
                const uint32_t bk = st + b_fb + kk * 4352;
#pragma unroll
                for (int mi = 0; mi < 4; mi++) {
                    LDM4T(Ahf[mi], ak + mi * 32);
                    LDM4T(Alf[mi], ak + A_TILE + mi * 32);
                }
#pragma unroll
                for (int p = 0; p < 4; p++) {
                    LDM4T(Bhf[p], bk + p * 32);
                    LDM4T(Blf[p], bk + B_TILE + p * 32);
                }
            } else {
                const uint32_t ak = st + a_fb + kk * 32;
                const uint32_t bk = st + b_fb + kk * 32;
#pragma unroll
                for (int mi = 0; mi < 4; mi++) {
                    LDM4(Ahf[mi], ak + mi * 1280);
                    LDM4(Alf[mi], ak + A_TILE + mi * 1280);
                }
#pragma unroll
                for (int p = 0; p < 4; p++) {
                    LDM4(Bhf[p], bk + p * 1280);
                    LDM4(Blf[p], bk + B_TILE + p * 1280);
                }
            }
            // pass hh
#pragma unroll
            for (int mi = 0; mi < 4; mi++)
#pragma unroll
                for (int nj = 0; nj < 8; nj++)
                    MMA16816(acc[mi][nj], Ahf[mi], Bhf[nj>>1][nj&1], Bhf[nj>>1][(nj&1)+2]);
            // pass hl
#pragma unroll
            for (int mi = 0; mi < 4; mi++)
#pragma unroll
                for (int nj = 0; nj < 8; nj++)
                    MMA16816(acc[mi][nj], Ahf[mi], Blf[nj>>1][nj&1], Blf[nj>>1][(nj&1)+2]);
            // pass lh
#pragma unroll
            for (int mi = 0; mi < 4; mi++)
#pragma unroll
                for (int nj = 0; nj < 8; nj++)
                    MMA16816(acc[mi][nj], Alf[mi], Bhf[nj>>1][nj&1], Bhf[nj>>1][(nj&1)+2]);
        }
        __syncthreads();
    }

    // epilogue
    const int qr = lid >> 2, qc = (lid & 3) * 2;
    const bool vmode = (n0 >= P.nsplit);
    const bool doBN = (P.bnPart != nullptr) && !vmode;
    float colS[16], colQ[16];
#pragma unroll
    for (int j = 0; j < 16; j++) { colS[j] = 0.f; colQ[j] = 0.f; }

#pragma unroll
    for (int mi = 0; mi < 4; mi++) {
        const int row0 = m0 + wm0 + mi * 16 + qr;
        const int row1 = row0 + 8;
#pragma unroll
        for (int nj = 0; nj < 8; nj++) {
            const int col = n0 + wn0 + nj * 8 + qc;
            float v00 = acc[mi][nj][0] * P.alpha;
            float v01 = acc[mi][nj][1] * P.alpha;
            float v10 = acc[mi][nj][2] * P.alpha;
            float v11 = acc[mi][nj][3] * P.alpha;
            if (vmode) {
                const int c0 = col - P.nsplit;
                if (P.bias) {
                    float b0 = P.bias[c0], b1 = P.bias[c0 + 1];
                    v00 += b0; v01 += b1; v10 += b0; v11 += b1;
                }
                ushort2 h0, l0, h1, l1;
                split2(v00, h0.x, l0.x); split2(v01, h0.y, l0.y);
                split2(v10, h1.x, l1.x); split2(v11, h1.y, l1.y);
                size_t o0 = (size_t)row0 * P.Nc + c0;
                size_t o1 = (size_t)row1 * P.Nc + c0;
                *reinterpret_cast<ushort2*>(P.Ch + o0) = h0;
                *reinterpret_cast<ushort2*>(P.Cl + o0) = l0;
                *reinterpret_cast<ushort2*>(P.Ch + o1) = h1;
                *reinterpret_cast<ushort2*>(P.Cl + o1) = l1;
            } else {
                float* Cb = P.C + (size_t)bz * P.sC;
                float2 a0, a1;
                a0.x = v00; a0.y = v01; a1.x = v10; a1.y = v11;
                *reinterpret_cast<float2*>(Cb + (size_t)row0 * P.Nc + col) = a0;
                *reinterpret_cast<float2*>(Cb + (size_t)row1 * P.Nc + col) = a1;
                if (doBN) {
                    colS[nj*2+0] += v00 + v10;
                    colS[nj*2+1] += v01 + v11;
                    colQ[nj*2+0] += v00*v00 + v10*v10;
                    colQ[nj*2+1] += v01*v01 + v11*v11;
                }
            }
        }
    }

    if (doBN) {
        // reduce across qr lanes (lanes differing in bits 2..4)
#pragma unroll
        for (int o = 4; o <= 16; o <<= 1) {
#pragma unroll
            for (int j = 0; j < 16; j++) {
                colS[j] += __shfl_xor_sync(0xffffffffu, colS[j], o);
                colQ[j] += __shfl_xor_sync(0xffffffffu, colQ[j], o);
            }
        }
        float* buf = (float*)smem;          // [2][128][2] floats = 2KB
        __syncthreads();
        if (lid < 4) {
            const int wm_idx = wid >> 1;    // 0: rows 0-63, 1: rows 64-127
#pragma unroll
            for (int nj = 0; nj < 8; nj++) {
#pragma unroll
                for (int e = 0; e < 2; e++) {
                    int cl = wn0 + nj * 8 + qc + e;      // 0..127
                    buf[(wm_idx * 128 + cl) * 2 + 0] = colS[nj*2+e];
                    buf[(wm_idx * 128 + cl) * 2 + 1] = colQ[nj*2+e];
                }
            }
        }
        __syncthreads();
        if (tid < 128) {
            float s = buf[tid*2+0] + buf[(128+tid)*2+0];
            float q = buf[tid*2+1] + buf[(128+tid)*2+1];
            int slot = bz * P.nby + by;
            float* p = P.bnPart + (size_t)slot * 2 * Cc;
            p[n0 + tid]      = s;
            p[Cc + n0 + tid] = q;
        }
    }
}

#define NT_SMEM (2*(2*10240 + 2*10240))   // 81920 -> 2 CTAs/SM
#define TN_SMEM (2*(2*8704  + 2*8704))    // 69632 -> 2 CTAs/SM

__global__ void __launch_bounds__(128, 2) gemm_nt(GP P) {
    extern __shared__ __align__(16) char smem[];
    gemm_body<false>(P, blockIdx.x, blockIdx.y, blockIdx.z, smem);
}
__global__ void __launch_bounds__(128, 2) gemm_tn(GP P) {
    extern __shared__ __align__(16) char smem[];
    gemm_body<true>(P, blockIdx.x, blockIdx.y, blockIdx.z, smem);
}

// ---------------- pack kernels ----------------
__global__ __launch_bounds__(256) void pack_weights(const float4* __restrict__ Wc,
                                                    const float4* __restrict__ Wo,
                                                    ushort4* __restrict__ H, ushort4* __restrict__ L)
{
    const long half = (long)Cc * Cc / 4;
    long i = (long)blockIdx.x * 256 + threadIdx.x;
    if (i >= 2 * half) return;
    float4 v = (i < half) ? Wc[i] : Wo[i - half];
    ushort4 h, l;
    split2(v.x, h.x, l.x); split2(v.y, h.y, l.y);
    split2(v.z, h.z, l.z); split2(v.w, h.w, l.w);
    H[i] = h; L[i] = l;
}

__global__ __launch_bounds__(256) void pack_split(const float4* __restrict__ X,
                                                  ushort4* __restrict__ H, ushort4* __restrict__ L, long n4)
{
    long i = (long)blockIdx.x * 256 + threadIdx.x;
    if (i >= n4) return;
    float4 v = X[i];
    ushort4 h, l;
    split2(v.x, h.x, l.x); split2(v.y, h.y, l.y);
    split2(v.z, h.z, l.z); split2(v.w, h.w, l.w);
    H[i] = h; L[i] = l;
}

__global__ __launch_bounds__(256) void pack_bn_relu(const float4* __restrict__ X,
                                                    ushort4* __restrict__ H, ushort4* __restrict__ L,
                                                    const float* __restrict__ g, const float* __restrict__ bb)
{
    long i = (long)blockIdx.x * 256 + threadIdx.x;   // over ROWS1*Cc/4
    float4 v = X[i];
    int ch = (int)((i * 4) % Cc);
    v.x = fmaxf(g[ch+0]*(v.x - g_mu1[ch+0])*g_rs1[ch+0] + bb[ch+0], 0.f);
    v.y = fmaxf(g[ch+1]*(v.y - g_mu1[ch+1])*g_rs1[ch+1] + bb[ch+1], 0.f);
    v.z = fmaxf(g[ch+2]*(v.z - g_mu1[ch+2])*g_rs1[ch+2] + bb[ch+2], 0.f);
    v.w = fmaxf(g[ch+3]*(v.w - g_mu1[ch+3])*g_rs1[ch+3] + bb[ch+3], 0.f);
    ushort4 h, l;
    split2(v.x, h.x, l.x); split2(v.y, h.y, l.y);
    split2(v.z, h.z, l.z); split2(v.w, h.w, l.w);
    H[i] = h; L[i] = l;
}

// ---------------- per-(b,t) column: softmax + K-th-largest radix select -> fp16 hi/lo ----------------
__global__ __launch_bounds__(256) void topk_softmax(const float* __restrict__ kvals,
                                                    ushrt* __restrict__ Wh, ushrt* __restrict__ Wl)
{
    const int b = blockIdx.x >> 9;
    const int t = blockIdx.x & 511;
    const size_t base = ((size_t)b * Tt + t) * Nn;
    const float* col = g_attn + base;
    const int tid = threadIdx.x;
    const int lid = tid & 31, wrp = tid >> 5;
    __shared__ float sh[8];
    __shared__ unsigned hist[256];
    __shared__ unsigned wtot[8];
    __shared__ unsigned s_sel, s_rem;

    float x[4]; unsigned u[4];
    float mx = -3.4e38f;
#pragma unroll
    for (int i = 0; i < 4; i++) {
        x[i] = col[tid + 256 * i];
        mx = fmaxf(mx, x[i]);
        unsigned bits = __float_as_uint(x[i]);
        u[i] = (bits & 0x80000000u) ? ~bits : (bits | 0x80000000u);
    }
    for (int o = 16; o > 0; o >>= 1) mx = fmaxf(mx, __shfl_xor_sync(0xffffffffu, mx, o));
    if (lid == 0) sh[wrp] = mx;
    __syncthreads();
    if (tid == 0) { float m = sh[0]; for (int i = 1; i < 8; i++) m = fmaxf(m, sh[i]); sh[0] = m; }
    __syncthreads();
    mx = sh[0];
    __syncthreads();
    float s = 0.f;
#pragma unroll
    for (int i = 0; i < 4; i++) s += expf(x[i] - mx);
    for (int o = 16; o > 0; o >>= 1) s += __shfl_xor_sync(0xffffffffu, s, o);
    if (lid == 0) sh[wrp] = s;
    __syncthreads();
    if (tid == 0) { float m = 0.f; for (int i = 0; i < 8; i++) m += sh[i]; sh[0] = m; }
    __syncthreads();
    const float inv = 1.f / sh[0];

    int K = (int)rintf((float)Nn * kvals[b]);
    if (K < 0) K = 0;
    if (K > Nn) K = Nn;
    if (K == 0) {
#pragma unroll
        for (int i = 0; i < 4; i++) { Wh[base + tid + 256*i] = 0; Wl[base + tid + 256*i] = 0; }
        return;
    }
    unsigned thr = 0u;
    if (K < Nn) {
        unsigned pref = 0u, rem = (unsigned)K;
        for (int shift = 24; shift >= 0; shift -= 8) {
            hist[tid] = 0u;
            __syncthreads();
            unsigned hm = (shift == 24) ? 0u : (0xFFFFFFFFu << (shift + 8));
#pragma unroll
            for (int i = 0; i < 4; i++)
                if ((u[i] & hm) == pref) atomicAdd(&hist[(u[i] >> shift) & 255u], 1u);
            __syncthreads();
            unsigned hv = hist[tid];
            unsigned v = hv;
#pragma unroll
            for (int o = 1; o < 32; o <<= 1) {
                unsigned tt = __shfl_down_sync(0xffffffffu, v, o);
                if (lid + o < 32) v += tt;
            }
            if (lid == 0) wtot[wrp] = v;
            __syncthreads();
            unsigned add = 0;
            for (int j = wrp + 1; j < 8; j++) add += wtot[j];
            v += add;
            unsigned nxt = v - hv;
            if (v >= rem && nxt < rem) { s_sel = (unsigned)tid; s_rem = rem - nxt; }
            __syncthreads();
            pref |= (s_sel << shift);
            rem = s_rem;
            __syncthreads();
        }
        thr = pref;
    }
#pragma unroll
    for (int i = 0; i < 4; i++) {
        float w = (u[i] >= thr) ? expf(x[i] - mx) * inv : 0.f;
        ushrt h, l;
        split2(w, h, l);
        Wh[base + tid + 256*i] = h;
        Wl[base + tid + 256*i] = l;
    }
}

// ---------------- BN finalize ----------------
__global__ void bn_finalize(const float* __restrict__ part, int nblk, float invN,
                            float* __restrict__ mu, float* __restrict__ rs)
{
    int c = blockIdx.x * 256 + threadIdx.x;
    if (c >= Cc) return;
    float s = 0.f, q = 0.f;
    for (int i = 0; i < nblk; i++) {
        s += part[(size_t)i * 2 * Cc + c];
        q += part[(size_t)i * 2 * Cc + Cc + c];
    }
    float m = s * invN;
    mu[c] = m;
    rs[c] = rsqrtf(q * invN - m * m + 1e-5f);
}

__global__ __launch_bounds__(256) void final_apply(float* __restrict__ out, const float* __restrict__ img,
                                                   const float* __restrict__ g, const float* __restrict__ bb)
{
    int i4 = blockIdx.x * 256 + threadIdx.x;
    float4 o = reinterpret_cast<float4*>(out)[i4];
    float4 im = reinterpret_cast<const float4*>(img)[i4];
    int c = (i4 * 4) % Cc;
    o.x = fmaxf(g[c+0]*(o.x - g_mu2[c+0])*g_rs2[c+0] + bb[c+0], 0.f) + im.x;
    o.y = fmaxf(g[c+1]*(o.y - g_mu2[c+1])*g_rs2[c+1] + bb[c+1], 0.f) + im.y;
    o.z = fmaxf(g[c+2]*(o.z - g_mu2[c+2])*g_rs2[c+2] + bb[c+2], 0.f) + im.z;
    o.w = fmaxf(g[c+3]*(o.w - g_mu2[c+3])*g_rs2[c+3] + bb[c+3], 0.f) + im.w;
    reinterpret_cast<float4*>(out)[i4] = o;
}

// ---------------- orchestration ----------------
extern "C" void kernel_launch(void* const* d_in, const int* in_sizes, int n_in,
                              void* d_out, int out_size)
{
    (void)in_sizes; (void)n_in; (void)out_size;
    const float* image = (const float*)d_in[0];
    const float* text  = (const float*)d_in[1];
    const float* kv    = (const float*)d_in[2];
    const float* Wc    = (const float*)d_in[3];
    const float* g1    = (const float*)d_in[5];
    const float* b1    = (const float*)d_in[6];
    const float* Wout  = (const float*)d_in[7];
    const float* bout  = (const float*)d_in[8];
    const float* g2    = (const float*)d_in[9];
    const float* b2    = (const float*)d_in[10];
    float* out = (float*)d_out;

    float *y1, *attn, *p1, *p2, *mu1, *rs1, *mu2, *rs2;
    ushrt *tx_h, *tx_l, *im_h, *im_l, *wcat_h, *wcat_l,
          *e1_h, *e1_l, *v_h, *v_l, *wt_h, *wt_l;
    cudaGetSymbolAddress((void**)&y1,   g_y1);
    cudaGetSymbolAddress((void**)&attn, g_attn);
    cudaGetSymbolAddress((void**)&p1,   g_p1);
    cudaGetSymbolAddress((void**)&p2,   g_p2);
    cudaGetSymbolAddress((void**)&mu1,  g_mu1);
    cudaGetSymbolAddress((void**)&rs1,  g_rs1);
    cudaGetSymbolAddress((void**)&mu2,  g_mu2);
    cudaGetSymbolAddress((void**)&rs2,  g_rs2);
    cudaGetSymbolAddress((void**)&tx_h, p_text_hi);  cudaGetSymbolAddress((void**)&tx_l, p_text_lo);
    cudaGetSymbolAddress((void**)&im_h, p_img_hi);   cudaGetSymbolAddress((void**)&im_l, p_img_lo);
    cudaGetSymbolAddress((void**)&wcat_h, p_Wcat_hi);cudaGetSymbolAddress((void**)&wcat_l, p_Wcat_lo);
    cudaGetSymbolAddress((void**)&e1_h, p_e1_hi);    cudaGetSymbolAddress((void**)&e1_l, p_e1_lo);
    cudaGetSymbolAddress((void**)&v_h,  p_v_hi);     cudaGetSymbolAddress((void**)&v_l,  p_v_lo);
    cudaGetSymbolAddress((void**)&wt_h, p_wt_hi);    cudaGetSymbolAddress((void**)&wt_l, p_wt_lo);

    cudaFuncSetAttribute(gemm_nt, cudaFuncAttributeMaxDynamicSharedMemorySize, NT_SMEM);
    cudaFuncSetAttribute(gemm_tn, cudaFuncAttributeMaxDynamicSharedMemorySize, TN_SMEM);

    const float inv_sqrtC = 0.03608439182435161f;  // 1/sqrt(768)

    // pack text + weights
    pack_split<<<6144, 256>>>((const float4*)text, (ushort4*)tx_h, (ushort4*)tx_l, (long)ROWS1*Cc/4);
    pack_weights<<<1152, 256>>>((const float4*)Wc, (const float4*)Wout, (ushort4*)wcat_h, (ushort4*)wcat_l);

    // merged G1G2 (one launch): C[8192,1536] = text @ [Wc;Wout]^T
    //   cols 0..767 -> y1 (fp32, + fused BN1 partials), cols 768..1535 -> v (split fp16) + bout bias
    GP Pm = { tx_h, tx_l, wcat_h, wcat_l,
              y1, v_h, v_l,
              Cc, Cc, Cc, Cc, 0, 0, 0, bout, 1.f, Cc, p1, 64 };
    gemm_nt<<<dim3(12, 64, 1), 128, NT_SMEM>>>(Pm);

    // pack image
    pack_split<<<12288, 256>>>((const float4*)image, (ushort4*)im_h, (ushort4*)im_l, (long)ROWS2*Cc/4);

    // BN1 finalize + fused BN+relu+split-pack of e1
    bn_finalize<<<3, 256>>>(p1, 64, 1.f/(float)ROWS1, mu1, rs1);
    pack_bn_relu<<<6144, 256>>>((const float4*)y1, (ushort4*)e1_h, (ushort4*)e1_l, g1, b1);

    // G3: attn_t[b][512,1024] = (e1[b] @ image[b]^T) / sqrt(C)
    GP P3 = { e1_h, e1_l, im_h, im_l, attn, nullptr, nullptr,
              Cc, Nn, Cc, Cc, (long)Tt*Cc, (long)Nn*Cc, (long)Tt*Nn, nullptr, inv_sqrtC, 1<<30,
              nullptr, 0 };
    gemm_nt<<<dim3(8, 4, Bb), 128, NT_SMEM>>>(P3);

    // masked softmax weights -> fp16 hi/lo in [b][t][n]
    topk_softmax<<<Bb*Tt, 256>>>(kv, wt_h, wt_l);

    // G4 (TN): out[b][1024,768] = sum_t w[b][t][n] * v[b][t][c]  + fused BN2 partials
    GP P4 = { wt_h, wt_l, v_h, v_l, out, nullptr, nullptr,
              Tt, Cc, Nn, Cc, (long)Tt*Nn, (long)Tt*Cc, (long)Nn*Cc, nullptr, 1.f, 1<<30,
              p2, 8 };
    gemm_tn<<<dim3(6, 8, Bb), 128, TN_SMEM>>>(P4);

    // BN2 finalize + final
    bn_finalize<<<3, 256>>>(p2, 128, 1.f/(float)ROWS2, mu2, rs2);
    final_apply<<<12288, 256>>>(out, image, g2, b2);
}